// round 2
// baseline (speedup 1.0000x reference)
#include <cuda_runtime.h>
#include <math.h>

// Problem constants (shapes are fixed by the dataset)
#define N_TOT 8192
#define D 128
#define TEMP_INV (1.0f/0.07f)
#define BM 128
#define BN 64
#define NCHUNK 16
#define JCHUNK (N_TOT/NCHUNK)   /* 512 */
#define SUBT (JCHUNK/BN)        /* 8   */
#define NBLK_M (N_TOT/BM)       /* 64  */
#define FIN_BLOCKS 32

// Scratch (no allocations allowed -> __device__ globals)
__device__ float g_G[2][D];
__device__ int   g_C[2];
__device__ int   g_valid[N_TOT];
__device__ float g_pm[NCHUNK][N_TOT];
__device__ float g_ps[NCHUNK][N_TOT];
__device__ float g_bsum[FIN_BLOCKS];
__device__ int   g_is64;

// ---------------------------------------------------------------------------
// Kernel 0: zero class sums/counts + detect whether labels are int64 or int32.
// Labels are {0,1}; if stored as little-endian int64, every odd 32-bit word is 0.
// ---------------------------------------------------------------------------
__global__ void init_detect_k(const int* __restrict__ lw) {
    int t = threadIdx.x;
    if (t < 2 * D) ((float*)g_G)[t] = 0.0f;
    if (t < 2)     g_C[t] = 0;

    int local = 0;
    for (int i = 1 + 2 * t; i < N_TOT; i += 2 * 256) local |= lw[i];
    __shared__ int anynz;
    if (t == 0) anynz = 0;
    __syncthreads();
    if (local) atomicOr(&anynz, 1);
    __syncthreads();
    if (t == 0) g_is64 = anynz ? 0 : 1;
}

// ---------------------------------------------------------------------------
// Kernel 1: valid mask + per-class feature sums G[c][k] and counts C[c].
// Block = 128 threads (one per k), each block covers 128 rows.
// ---------------------------------------------------------------------------
__global__ void prep_k(const float* __restrict__ f, const int* __restrict__ lw) {
    int k  = threadIdx.x;             // 0..127
    int r0 = blockIdx.x * 128;
    int is64 = g_is64;
    float a0 = 0.f, a1 = 0.f;
    int c0 = 0, c1 = 0;
    for (int r = 0; r < 128; r++) {
        int row = r0 + r;
        float v = f[(size_t)row * D + k];
        int nz = __syncthreads_or(v != 0.0f);
        if (k == 0) g_valid[row] = nz;
        if (nz) {
            int lab = is64 ? lw[2 * row] : lw[row];
            if (lab == 0) a0 += v; else a1 += v;
            if (k == 0) { if (lab == 0) c0++; else c1++; }
        }
    }
    atomicAdd(&g_G[0][k], a0);
    atomicAdd(&g_G[1][k], a1);
    if (k == 0) { atomicAdd(&g_C[0], c0); atomicAdd(&g_C[1], c1); }
}

// ---------------------------------------------------------------------------
// Kernel 2: the big one. Tiled f * f^T with fused online logsumexp.
// Grid (64 anchor tiles, 16 J-chunks). Block 256 threads.
// SMEM: As[k][m] 128x128, Bs[k][n] 128x64 (both k-major, conflict-free inner LDS),
// Bv[64] valid flags. 96.25 KB dynamic -> 2 blocks/SM.
// Each thread: 8 anchors x 4 cols micro-tile; online (max, sumexp) per anchor row;
// shfl-combined across the 16 lanes sharing a row; partial written per chunk.
// ---------------------------------------------------------------------------
__global__ void __launch_bounds__(256) lse_k(const float* __restrict__ f) {
    extern __shared__ float sm[];
    float* As = sm;                     // [D][BM]
    float* Bs = sm + D * BM;            // [D][BN]
    int*   Bv = (int*)(Bs + D * BN);    // [BN]

    const int tid = threadIdx.x;
    const int tx  = tid & 15;           // column group
    const int ty  = tid >> 4;           // row group
    const int gm0 = blockIdx.x * BM;
    const int j0  = blockIdx.y * JCHUNK;

    // Fill A transposed (STS conflict-free: lanes vary m)
    #pragma unroll
    for (int it = 0; it < 16; ++it) {
        int idx = tid + it * 256;
        int m = idx & 127, kq = idx >> 7;
        float4 v = *(const float4*)(f + (size_t)(gm0 + m) * D + kq * 4);
        As[(kq * 4 + 0) * BM + m] = v.x;
        As[(kq * 4 + 1) * BM + m] = v.y;
        As[(kq * 4 + 2) * BM + m] = v.z;
        As[(kq * 4 + 3) * BM + m] = v.w;
    }

    float mrun[8], srun[8];
    #pragma unroll
    for (int r = 0; r < 8; r++) { mrun[r] = -INFINITY; srun[r] = 0.f; }

    for (int jt = 0; jt < SUBT; ++jt) {
        int gj0 = j0 + jt * BN;
        __syncthreads();   // prev compute done reading Bs (and A fill visible on jt==0)
        #pragma unroll
        for (int it = 0; it < 8; ++it) {
            int idx = tid + it * 256;
            int n = idx & 63, kq = idx >> 6;
            float4 v = *(const float4*)(f + (size_t)(gj0 + n) * D + kq * 4);
            Bs[(kq * 4 + 0) * BN + n] = v.x;
            Bs[(kq * 4 + 1) * BN + n] = v.y;
            Bs[(kq * 4 + 2) * BN + n] = v.z;
            Bs[(kq * 4 + 3) * BN + n] = v.w;
        }
        if (tid < BN) Bv[tid] = g_valid[gj0 + tid];
        __syncthreads();

        float acc[8][4];
        #pragma unroll
        for (int r = 0; r < 8; r++)
            #pragma unroll
            for (int c = 0; c < 4; c++) acc[r][c] = 0.f;

        #pragma unroll 8
        for (int k = 0; k < D; k++) {
            float4 a0 = *(const float4*)(As + k * BM + ty * 8);
            float4 a1 = *(const float4*)(As + k * BM + ty * 8 + 4);
            float4 b  = *(const float4*)(Bs + k * BN + tx * 4);
            float av[8] = {a0.x, a0.y, a0.z, a0.w, a1.x, a1.y, a1.z, a1.w};
            float bv[4] = {b.x, b.y, b.z, b.w};
            #pragma unroll
            for (int r = 0; r < 8; r++)
                #pragma unroll
                for (int c = 0; c < 4; c++)
                    acc[r][c] = fmaf(av[r], bv[c], acc[r][c]);
        }

        int ok0 = Bv[tx * 4 + 0], ok1 = Bv[tx * 4 + 1];
        int ok2 = Bv[tx * 4 + 2], ok3 = Bv[tx * 4 + 3];
        #pragma unroll
        for (int r = 0; r < 8; r++) {
            float v0 = acc[r][0] * TEMP_INV, v1 = acc[r][1] * TEMP_INV;
            float v2 = acc[r][2] * TEMP_INV, v3 = acc[r][3] * TEMP_INV;
            float tmax = -INFINITY;
            if (ok0) tmax = fmaxf(tmax, v0);
            if (ok1) tmax = fmaxf(tmax, v1);
            if (ok2) tmax = fmaxf(tmax, v2);
            if (ok3) tmax = fmaxf(tmax, v3);
            if (tmax > mrun[r]) {            // __expf(-inf) == 0, safe when mrun=-inf
                srun[r] *= __expf(mrun[r] - tmax);
                mrun[r] = tmax;
            }
            float s = srun[r];
            if (ok0) s += __expf(v0 - mrun[r]);
            if (ok1) s += __expf(v1 - mrun[r]);
            if (ok2) s += __expf(v2 - mrun[r]);
            if (ok3) s += __expf(v3 - mrun[r]);
            srun[r] = s;
        }
    }

    // Combine (m, s) across the 16 lanes (tx) owning the same anchor rows.
    #pragma unroll
    for (int r = 0; r < 8; r++) {
        float m = mrun[r], s = srun[r];
        #pragma unroll
        for (int off = 8; off > 0; off >>= 1) {
            float m2 = __shfl_xor_sync(0xffffffffu, m, off, 16);
            float s2 = __shfl_xor_sync(0xffffffffu, s, off, 16);
            float M = fmaxf(m, m2);
            float sn;
            if (M == -INFINITY) sn = 0.f;
            else sn = ((m  == -INFINITY) ? 0.f : s  * __expf(m  - M))
                    + ((m2 == -INFINITY) ? 0.f : s2 * __expf(m2 - M));
            m = M; s = sn;
        }
        if (tx == 0) {
            int anchor = gm0 + ty * 8 + r;
            g_pm[blockIdx.y][anchor] = m;
            g_ps[blockIdx.y][anchor] = s;
        }
    }
}

// ---------------------------------------------------------------------------
// Kernel 3: per-anchor finalize. Combine NCHUNK partials -> lse; dot with G;
// term_i = (C[lab]*lse_i - dot(f_i,G[lab])/T) / 128 (valid anchors only).
// Deterministic block tree-sum -> g_bsum.
// ---------------------------------------------------------------------------
__global__ void fin_k(const float* __restrict__ f, const int* __restrict__ lw) {
    __shared__ float Gs[2 * D];
    __shared__ float red[256];
    int t = threadIdx.x;
    Gs[t] = ((const float*)g_G)[t];
    __syncthreads();

    int i = blockIdx.x * 256 + t;
    float M = -INFINITY, S = 0.f;
    #pragma unroll
    for (int c = 0; c < NCHUNK; c++) {
        float m2 = g_pm[c][i], s2 = g_ps[c][i];
        float Mn = fmaxf(M, m2);
        float Sn;
        if (Mn == -INFINITY) Sn = 0.f;
        else Sn = ((M  == -INFINITY) ? 0.f : S  * __expf(M  - Mn))
                + ((m2 == -INFINITY) ? 0.f : s2 * __expf(m2 - Mn));
        M = Mn; S = Sn;
    }

    float term = 0.f;
    if (g_valid[i]) {
        float lse = M + logf(S);
        int lab = g_is64 ? lw[2 * i] : lw[i];
        const float4* fr = (const float4*)(f + (size_t)i * D);
        const float4* gr = (const float4*)(Gs + lab * D);
        float dot = 0.f;
        #pragma unroll
        for (int k = 0; k < D / 4; k++) {
            float4 a = fr[k]; float4 g = gr[k];
            dot = fmaf(a.x, g.x, dot); dot = fmaf(a.y, g.y, dot);
            dot = fmaf(a.z, g.z, dot); dot = fmaf(a.w, g.w, dot);
        }
        float cnt = (float)g_C[lab];
        term = (cnt * lse - dot * TEMP_INV) * (1.0f / 128.0f);
    }
    red[t] = term;
    __syncthreads();
    for (int st = 128; st > 0; st >>= 1) {
        if (t < st) red[t] += red[t + st];
        __syncthreads();
    }
    if (t == 0) g_bsum[blockIdx.x] = red[0];
}

// Kernel 4: deterministic final sum -> loss = sum/b, b = 256.
__global__ void fin2_k(float* out) {
    if (threadIdx.x == 0) {
        float s = 0.f;
        for (int i = 0; i < FIN_BLOCKS; i++) s += g_bsum[i];
        out[0] = s * (1.0f / 256.0f);
    }
}

// ---------------------------------------------------------------------------
extern "C" void kernel_launch(void* const* d_in, const int* in_sizes, int n_in,
                              void* d_out, int out_size) {
    const float* f  = (const float*)d_in[0];
    const int*   lw = (const int*)d_in[1];   // labels viewed as 32-bit words
    float* out = (float*)d_out;

    const int SMEM_BYTES = (D * BM + D * BN + BN) * 4;  // 98560 B
    cudaFuncSetAttribute(lse_k, cudaFuncAttributeMaxDynamicSharedMemorySize, SMEM_BYTES);

    init_detect_k<<<1, 256>>>(lw);
    prep_k<<<NBLK_M, 128>>>(f, lw);
    lse_k<<<dim3(NBLK_M, NCHUNK), 256, SMEM_BYTES>>>(f);
    fin_k<<<FIN_BLOCKS, 256>>>(f, lw);
    fin2_k<<<1, 32>>>(out);
}

// round 4
// speedup vs baseline: 1.8154x; 1.8154x over previous
#include <cuda_runtime.h>
#include <cuda_bf16.h>
#include <math.h>
#include <stdint.h>

// ---------------------------------------------------------------------------
// Problem constants
// ---------------------------------------------------------------------------
#define N_TOT 8192
#define D 128
#define TEMP_INV (1.0f/0.07f)
#define TILE 128
#define NI 64          /* I tiles */
#define NJG 2          /* J groups (grid.y) */
#define NJ 32          /* J tiles per CTA */
#define FIN_BLOCKS 32

// SMEM tile geometry: 128 rows x 128 bf16, padded row stride 136 elem (272 B)
#define PKB 272                    /* padded row stride, bytes */
#define TB  (128 * PKB)            /* 34816 B per matrix */
#define OFF_A_HI 0
#define OFF_A_LO TB
#define OFF_B(b) (2*TB + (b)*(2*TB))   /* hi at +0, lo at +TB */
#define OFF_BM   (6*TB)                /* 4 x uint32 col-valid mask */
#define SMEM_BYTES (6*TB + 64)         /* 208960 */

// ---------------------------------------------------------------------------
// Device scratch (no allocations allowed)
// ---------------------------------------------------------------------------
__device__ __nv_bfloat16 g_hi[N_TOT * D];
__device__ __nv_bfloat16 g_lo[N_TOT * D];
__device__ float g_G[2][D];
__device__ int   g_C[2];
__device__ int   g_valid[N_TOT];
__device__ float g_pm[NJG][N_TOT];
__device__ float g_ps[NJG][N_TOT];
__device__ float g_bsum[FIN_BLOCKS];
__device__ int   g_is64;

// ---------------------------------------------------------------------------
// Family-safe PTX helpers (no sm_103a-only instructions!)
// ---------------------------------------------------------------------------
__device__ __forceinline__ uint32_t smem_u32(const void* p) {
    uint32_t a;
    asm("{ .reg .u64 t; cvta.to.shared.u64 t, %1; cvt.u32.u64 %0, t; }" : "=r"(a) : "l"(p));
    return a;
}
__device__ __forceinline__ void ldsm4(uint32_t* r, uint32_t addr) {
    asm volatile("ldmatrix.sync.aligned.m8n8.x4.shared.b16 {%0,%1,%2,%3}, [%4];"
                 : "=r"(r[0]), "=r"(r[1]), "=r"(r[2]), "=r"(r[3]) : "r"(addr));
}
__device__ __forceinline__ void mma16816(float* c, const uint32_t* a, uint32_t b0, uint32_t b1) {
    asm volatile("mma.sync.aligned.m16n8k16.row.col.f32.bf16.bf16.f32 "
                 "{%0,%1,%2,%3}, {%4,%5,%6,%7}, {%8,%9}, {%0,%1,%2,%3};"
                 : "+f"(c[0]), "+f"(c[1]), "+f"(c[2]), "+f"(c[3])
                 : "r"(a[0]), "r"(a[1]), "r"(a[2]), "r"(a[3]), "r"(b0), "r"(b1));
}
__device__ __forceinline__ void cp16(uint32_t dst, const void* src) {
    asm volatile("cp.async.cg.shared.global [%0], [%1], 16;" :: "r"(dst), "l"(src));
}
#define CP_COMMIT() asm volatile("cp.async.commit_group;" ::: "memory")
#define CP_WAIT(n)  asm volatile("cp.async.wait_group %0;" :: "n"(n) : "memory")

// online-softmax merge of (m,s) pairs
__device__ __forceinline__ void comb(float& m, float& s, float m2, float s2) {
    float M = fmaxf(m, m2);
    float S;
    if (M == -INFINITY) S = 0.f;
    else S = ((m  == -INFINITY) ? 0.f : s  * __expf(m  - M))
           + ((m2 == -INFINITY) ? 0.f : s2 * __expf(m2 - M));
    m = M; s = S;
}

// Issue cp.async for one 128x128 bf16 tile into padded smem layout.
__device__ __forceinline__ void cp_tile(const __nv_bfloat16* __restrict__ src, int rowBase,
                                        uint32_t dstBase, int tid) {
    #pragma unroll
    for (int it = 0; it < 8; ++it) {
        int i = tid + it * 256;
        int row = i >> 4, c = i & 15;           // c = 16B chunk (8 bf16)
        cp16(dstBase + row * PKB + c * 16, src + (size_t)(rowBase + row) * D + c * 8);
    }
}

// ---------------------------------------------------------------------------
// Kernel 0: zero class sums/counts + detect int64 vs int32 labels.
// ---------------------------------------------------------------------------
__global__ void init_detect_k(const int* __restrict__ lw) {
    int t = threadIdx.x;
    if (t < 2 * D) ((float*)g_G)[t] = 0.0f;
    if (t < 2)     g_C[t] = 0;
    int local = 0;
    for (int i = 1 + 2 * t; i < N_TOT; i += 2 * 256) local |= lw[i];
    __shared__ int anynz;
    if (t == 0) anynz = 0;
    __syncthreads();
    if (local) atomicOr(&anynz, 1);
    __syncthreads();
    if (t == 0) g_is64 = anynz ? 0 : 1;
}

// ---------------------------------------------------------------------------
// Kernel 1: bf16 hi/lo split + valid mask. One block (128 thr) per row.
// ---------------------------------------------------------------------------
__global__ void cvt_k(const float* __restrict__ f) {
    int row = blockIdx.x, k = threadIdx.x;
    size_t i = (size_t)row * D + k;
    float v = f[i];
    __nv_bfloat16 h = __float2bfloat16(v);
    g_hi[i] = h;
    g_lo[i] = __float2bfloat16(v - __bfloat162float(h));
    int nz = __syncthreads_or(v != 0.0f);
    if (k == 0) g_valid[row] = nz;
}

// ---------------------------------------------------------------------------
// Kernel 2: per-class feature sums/counts (valid mask precomputed -> no bars).
// ---------------------------------------------------------------------------
__global__ void prep_k(const float* __restrict__ f, const int* __restrict__ lw) {
    int k  = threadIdx.x;
    int r0 = blockIdx.x * 128;
    int is64 = g_is64;
    float a0 = 0.f, a1 = 0.f;
    int c0 = 0, c1 = 0;
    for (int r = 0; r < 128; r++) {
        int row = r0 + r;
        if (g_valid[row]) {
            int lab = is64 ? lw[2 * row] : lw[row];
            float v = f[(size_t)row * D + k];
            if (lab == 0) a0 += v; else a1 += v;
            if (k == 0) { if (lab == 0) c0++; else c1++; }
        }
    }
    atomicAdd(&g_G[0][k], a0);
    atomicAdd(&g_G[1][k], a1);
    if (k == 0) { atomicAdd(&g_C[0], c0); atomicAdd(&g_C[1], c1); }
}

// ---------------------------------------------------------------------------
// Kernel 3: bf16-split GEMM via mma.sync (HMMA) + fused online logsumexp.
// grid (NI, NJG), 256 threads (8 warps). Each warp owns 16 anchor rows.
// A hi/lo resident; B hi/lo double-buffered via cp.async.
// ---------------------------------------------------------------------------
__global__ void __launch_bounds__(256, 1) lse_mma_k() {
    extern __shared__ char smc[];
    const uint32_t base = smem_u32(smc);
    uint32_t* Bm = (uint32_t*)(smc + OFF_BM);

    const int tid  = threadIdx.x;
    const int wid  = tid >> 5;
    const int lane = tid & 31;
    const int rowI = blockIdx.x * TILE;
    const int jtile0 = blockIdx.y * NJ;
    const int wrow = wid * 16;

    // ldmatrix per-lane row mapping (shared by A and B operand addressing):
    // lanes 0-7: mat0 rows, 8-15: mat1 (+8 rows), 16-31: k+8 halves
    const int lrow = (lane & 7) + ((lane >> 3) & 1) * 8;
    const int lkof = (lane >> 4) * 16;

    const uint32_t aHiB = base + OFF_A_HI + (wrow + lrow) * PKB + lkof;
    const uint32_t aLoB = base + OFF_A_LO + (wrow + lrow) * PKB + lkof;

    // prologue: A hi/lo + B tile0 hi/lo in one cp.async group
    cp_tile(g_hi, rowI, base + OFF_A_HI, tid);
    cp_tile(g_lo, rowI, base + OFF_A_LO, tid);
    cp_tile(g_hi, jtile0 * TILE, base + OFF_B(0), tid);
    cp_tile(g_lo, jtile0 * TILE, base + OFF_B(0) + TB, tid);
    CP_COMMIT();

    float m0 = -INFINITY, s0 = 0.f;   // row  wrow + lane/4
    float m1 = -INFINITY, s1 = 0.f;   // row  wrow + lane/4 + 8

    for (int jt = 0; jt < NJ; jt++) {
        const int p = jt & 1, q = p ^ 1;
        const int jb = (jtile0 + jt) * TILE;

        if (jt + 1 < NJ) {
            int jb2 = jb + TILE;
            cp_tile(g_hi, jb2, base + OFF_B(q), tid);
            cp_tile(g_lo, jb2, base + OFF_B(q) + TB, tid);
            CP_COMMIT();
            CP_WAIT(1);
        } else {
            CP_WAIT(0);
        }

        if (tid < 128) {  // column-valid bitmask for this J tile
            int v = g_valid[jb + tid];
            uint32_t bal = __ballot_sync(0xffffffffu, v != 0);
            if (lane == 0) Bm[tid >> 5] = bal;
        }
        __syncthreads();

        // ---- GEMM: acc = Ahi*Bhi^T + Alo*Bhi^T + Ahi*Blo^T ----
        float acc[16][4];
        #pragma unroll
        for (int nt = 0; nt < 16; nt++)
            #pragma unroll
            for (int c = 0; c < 4; c++) acc[nt][c] = 0.f;

        const uint32_t bHiB = base + OFF_B(p) + lrow * PKB + lkof;
        const uint32_t bLoB = bHiB + TB;

        #pragma unroll
        for (int ks = 0; ks < 8; ks++) {
            uint32_t aH[4], aL[4];
            ldsm4(aH, aHiB + ks * 32);
            ldsm4(aL, aLoB + ks * 32);
            #pragma unroll
            for (int nt2 = 0; nt2 < 8; nt2++) {
                uint32_t bH[4], bL[4];
                ldsm4(bH, bHiB + nt2 * (16 * PKB) + ks * 32);
                mma16816(acc[nt2 * 2 + 0], aH, bH[0], bH[2]);
                mma16816(acc[nt2 * 2 + 1], aH, bH[1], bH[3]);
                mma16816(acc[nt2 * 2 + 0], aL, bH[0], bH[2]);
                mma16816(acc[nt2 * 2 + 1], aL, bH[1], bH[3]);
                ldsm4(bL, bLoB + nt2 * (16 * PKB) + ks * 32);
                mma16816(acc[nt2 * 2 + 0], aH, bL[0], bL[2]);
                mma16816(acc[nt2 * 2 + 1], aH, bL[1], bL[3]);
            }
        }

        // ---- epilogue: masked online (max, sum-exp) on C fragments ----
        // acc[nt]: c0,c1 -> (r0, cn),(r0,cn+1); c2,c3 -> (r0+8, cn),(r0+8,cn+1)
        float tm0 = -INFINITY, tm1 = -INFINITY;
        #pragma unroll
        for (int nt = 0; nt < 16; nt++) {
            int cn = nt * 8 + (lane & 3) * 2;
            uint32_t mk = (Bm[cn >> 5] >> (cn & 31)) & 3u;
            float v0 = acc[nt][0] * TEMP_INV; acc[nt][0] = v0;
            float v1 = acc[nt][1] * TEMP_INV; acc[nt][1] = v1;
            float v2 = acc[nt][2] * TEMP_INV; acc[nt][2] = v2;
            float v3 = acc[nt][3] * TEMP_INV; acc[nt][3] = v3;
            if (mk & 1u) { tm0 = fmaxf(tm0, v0); tm1 = fmaxf(tm1, v2); }
            if (mk & 2u) { tm0 = fmaxf(tm0, v1); tm1 = fmaxf(tm1, v3); }
        }
        if (tm0 > m0) { s0 *= __expf(m0 - tm0); m0 = tm0; }
        if (tm1 > m1) { s1 *= __expf(m1 - tm1); m1 = tm1; }
        float a0 = 0.f, a1 = 0.f;
        #pragma unroll
        for (int nt = 0; nt < 16; nt++) {
            int cn = nt * 8 + (lane & 3) * 2;
            uint32_t mk = (Bm[cn >> 5] >> (cn & 31)) & 3u;
            if (mk & 1u) { a0 += __expf(acc[nt][0] - m0); a1 += __expf(acc[nt][2] - m1); }
            if (mk & 2u) { a0 += __expf(acc[nt][1] - m0); a1 += __expf(acc[nt][3] - m1); }
        }
        s0 += a0; s1 += a1;
        __syncthreads();   // done reading buf p + Bm before next prefetch/ballot
    }

    // combine across the 4 lanes of each quad (same output rows)
    #pragma unroll
    for (int off = 1; off <= 2; off <<= 1) {
        float mm = __shfl_xor_sync(0xffffffffu, m0, off);
        float ss = __shfl_xor_sync(0xffffffffu, s0, off);
        comb(m0, s0, mm, ss);
        mm = __shfl_xor_sync(0xffffffffu, m1, off);
        ss = __shfl_xor_sync(0xffffffffu, s1, off);
        comb(m1, s1, mm, ss);
    }
    if ((lane & 3) == 0) {
        int row = rowI + wrow + (lane >> 2);
        g_pm[blockIdx.y][row]     = m0;
        g_ps[blockIdx.y][row]     = s0;
        g_pm[blockIdx.y][row + 8] = m1;
        g_ps[blockIdx.y][row + 8] = s1;
    }
}

// ---------------------------------------------------------------------------
// Kernel 4: per-anchor finalize (combine NJG partials, dot with G, block sums).
// ---------------------------------------------------------------------------
__global__ void fin_k(const float* __restrict__ f, const int* __restrict__ lw) {
    __shared__ float Gs[2 * D];
    __shared__ float red[256];
    int t = threadIdx.x;
    Gs[t] = ((const float*)g_G)[t];
    __syncthreads();

    int i = blockIdx.x * 256 + t;
    float M = g_pm[0][i], S = g_ps[0][i];
    comb(M, S, g_pm[1][i], g_ps[1][i]);

    float term = 0.f;
    if (g_valid[i]) {
        float lse = M + logf(S);
        int lab = g_is64 ? lw[2 * i] : lw[i];
        const float4* fr = (const float4*)(f + (size_t)i * D);
        const float4* gr = (const float4*)(Gs + lab * D);
        float dot = 0.f;
        #pragma unroll
        for (int k = 0; k < D / 4; k++) {
            float4 a = fr[k]; float4 g = gr[k];
            dot = fmaf(a.x, g.x, dot); dot = fmaf(a.y, g.y, dot);
            dot = fmaf(a.z, g.z, dot); dot = fmaf(a.w, g.w, dot);
        }
        float cnt = (float)g_C[lab];
        term = (cnt * lse - dot * TEMP_INV) * (1.0f / 128.0f);
    }
    red[t] = term;
    __syncthreads();
    for (int st = 128; st > 0; st >>= 1) {
        if (t < st) red[t] += red[t + st];
        __syncthreads();
    }
    if (t == 0) g_bsum[blockIdx.x] = red[0];
}

__global__ void fin2_k(float* out) {
    if (threadIdx.x == 0) {
        float s = 0.f;
        for (int i = 0; i < FIN_BLOCKS; i++) s += g_bsum[i];
        out[0] = s * (1.0f / 256.0f);
    }
}

// ---------------------------------------------------------------------------
extern "C" void kernel_launch(void* const* d_in, const int* in_sizes, int n_in,
                              void* d_out, int out_size) {
    const float* f  = (const float*)d_in[0];
    const int*   lw = (const int*)d_in[1];
    float* out = (float*)d_out;

    cudaFuncSetAttribute(lse_mma_k, cudaFuncAttributeMaxDynamicSharedMemorySize, SMEM_BYTES);

    init_detect_k<<<1, 256>>>(lw);
    cvt_k<<<N_TOT, 128>>>(f);
    prep_k<<<NI, 128>>>(f, lw);
    lse_mma_k<<<dim3(NI, NJG), 256, SMEM_BYTES>>>();
    fin_k<<<FIN_BLOCKS, 256>>>(f, lw);
    fin2_k<<<1, 32>>>(out);
}

// round 5
// speedup vs baseline: 2.2867x; 1.2596x over previous
#include <cuda_runtime.h>
#include <cuda_bf16.h>
#include <math.h>
#include <stdint.h>

// ---------------------------------------------------------------------------
// Problem constants
// ---------------------------------------------------------------------------
#define N_TOT 8192
#define D 128
#define TEMP_INV (1.0f/0.07f)
#define SCALE_LOG2 (1.44269504088896340736f/0.07f)   /* log2(e)/T */
#define LN2F 0.6931471805599453f
#define TILE 128
#define NI 64          /* I tiles */
#define NJG 2          /* J groups (grid.y) */
#define NJ 32          /* J tiles per CTA */
#define FIN_BLOCKS 32

// SMEM tile geometry: 128 rows x 128 bf16, padded row stride 136 elem (272 B)
#define PKB 272
#define TB  (128 * PKB)
#define OFF_A_HI 0
#define OFF_A_LO TB
#define OFF_B(b) (2*TB + (b)*(2*TB))   /* hi at +0, lo at +TB */
#define SMEM_BYTES (6*TB)              /* 208896 */

// ---------------------------------------------------------------------------
// Device scratch
// ---------------------------------------------------------------------------
__device__ __nv_bfloat16 g_hi[N_TOT * D];
__device__ __nv_bfloat16 g_lo[N_TOT * D];
__device__ float    g_G[2][D];
__device__ int      g_C[2];
__device__ int      g_valid[N_TOT];
__device__ uint32_t g_vmask[N_TOT / 32];
__device__ float    g_pm[NJG][N_TOT];   /* log2-domain running max */
__device__ float    g_ps[NJG][N_TOT];
__device__ float    g_bsum[FIN_BLOCKS];
__device__ int      g_is64;

// ---------------------------------------------------------------------------
// Family-safe PTX helpers
// ---------------------------------------------------------------------------
__device__ __forceinline__ uint32_t smem_u32(const void* p) {
    uint32_t a;
    asm("{ .reg .u64 t; cvta.to.shared.u64 t, %1; cvt.u32.u64 %0, t; }" : "=r"(a) : "l"(p));
    return a;
}
__device__ __forceinline__ void ldsm4(uint32_t* r, uint32_t addr) {
    asm volatile("ldmatrix.sync.aligned.m8n8.x4.shared.b16 {%0,%1,%2,%3}, [%4];"
                 : "=r"(r[0]), "=r"(r[1]), "=r"(r[2]), "=r"(r[3]) : "r"(addr));
}
__device__ __forceinline__ void mma16816(float* c, const uint32_t* a, uint32_t b0, uint32_t b1) {
    asm volatile("mma.sync.aligned.m16n8k16.row.col.f32.bf16.bf16.f32 "
                 "{%0,%1,%2,%3}, {%4,%5,%6,%7}, {%8,%9}, {%0,%1,%2,%3};"
                 : "+f"(c[0]), "+f"(c[1]), "+f"(c[2]), "+f"(c[3])
                 : "r"(a[0]), "r"(a[1]), "r"(a[2]), "r"(a[3]), "r"(b0), "r"(b1));
}
__device__ __forceinline__ void cp16(uint32_t dst, const void* src) {
    asm volatile("cp.async.cg.shared.global [%0], [%1], 16;" :: "r"(dst), "l"(src));
}
#define CP_COMMIT() asm volatile("cp.async.commit_group;" ::: "memory")
#define CP_WAIT(n)  asm volatile("cp.async.wait_group %0;" :: "n"(n) : "memory")

__device__ __forceinline__ float ex2(float x) {
    float y;
    asm("ex2.approx.ftz.f32 %0, %1;" : "=f"(y) : "f"(x));
    return y;
}

// online-softmax merge, log2 domain
__device__ __forceinline__ void comb2(float& m, float& s, float m2, float s2) {
    float M = fmaxf(m, m2);
    float S;
    if (M == -INFINITY) S = 0.f;
    else S = ((m  == -INFINITY) ? 0.f : s  * ex2(m  - M))
           + ((m2 == -INFINITY) ? 0.f : s2 * ex2(m2 - M));
    m = M; s = S;
}

__device__ __forceinline__ void cp_tile(const __nv_bfloat16* __restrict__ src, int rowBase,
                                        uint32_t dstBase, int tid) {
    #pragma unroll
    for (int it = 0; it < 8; ++it) {
        int i = tid + it * 256;
        int row = i >> 4, c = i & 15;
        cp16(dstBase + row * PKB + c * 16, src + (size_t)(rowBase + row) * D + c * 8);
    }
}

// ---------------------------------------------------------------------------
// Kernel 0: zero class sums/counts + detect int64 vs int32 labels.
// ---------------------------------------------------------------------------
__global__ void init_detect_k(const int* __restrict__ lw) {
    int t = threadIdx.x;
    if (t < 2 * D) ((float*)g_G)[t] = 0.0f;
    if (t < 2)     g_C[t] = 0;
    int local = 0;
    for (int i = 1 + 2 * t; i < N_TOT; i += 2 * 256) local |= lw[i];
    __shared__ int anynz;
    if (t == 0) anynz = 0;
    __syncthreads();
    if (local) atomicOr(&anynz, 1);
    __syncthreads();
    if (t == 0) g_is64 = anynz ? 0 : 1;
}

// ---------------------------------------------------------------------------
// Kernel 1: bf16 hi/lo split + valid flag. One 128-thread block per row.
// ---------------------------------------------------------------------------
__global__ void cvt_k(const float* __restrict__ f) {
    int row = blockIdx.x, k = threadIdx.x;
    size_t i = (size_t)row * D + k;
    float v = f[i];
    __nv_bfloat16 h = __float2bfloat16(v);
    g_hi[i] = h;
    g_lo[i] = __float2bfloat16(v - __bfloat162float(h));
    int nz = __syncthreads_or(v != 0.0f);
    if (k == 0) g_valid[row] = nz;
}

// Kernel 1b: pack valid flags into bitmask words.
__global__ void vmask_k() {
    int i = blockIdx.x * 256 + threadIdx.x;
    uint32_t b = __ballot_sync(0xffffffffu, g_valid[i] != 0);
    if ((threadIdx.x & 31) == 0) g_vmask[i >> 5] = b;
}

// ---------------------------------------------------------------------------
// Kernel 2: per-class feature sums/counts.
// ---------------------------------------------------------------------------
__global__ void prep_k(const float* __restrict__ f, const int* __restrict__ lw) {
    int k  = threadIdx.x;
    int r0 = blockIdx.x * 128;
    int is64 = g_is64;
    float a0 = 0.f, a1 = 0.f;
    int c0 = 0, c1 = 0;
    for (int r = 0; r < 128; r++) {
        int row = r0 + r;
        if (g_valid[row]) {
            int lab = is64 ? lw[2 * row] : lw[row];
            float v = f[(size_t)row * D + k];
            if (lab == 0) a0 += v; else a1 += v;
            if (k == 0) { if (lab == 0) c0++; else c1++; }
        }
    }
    atomicAdd(&g_G[0][k], a0);
    atomicAdd(&g_G[1][k], a1);
    if (k == 0) { atomicAdd(&g_C[0], c0); atomicAdd(&g_C[1], c1); }
}

// ---------------------------------------------------------------------------
// Kernel 3: bf16-split GEMM (HMMA) + fused online logsumexp (log2 domain).
// grid (NI, NJG), 256 threads. One __syncthreads per J-tile; epilogue is
// register-only and overlaps the next tile's cp.async.
// ---------------------------------------------------------------------------
__global__ void __launch_bounds__(256, 1) lse_mma_k() {
    extern __shared__ char smc[];
    const uint32_t base = smem_u32(smc);

    const int tid  = threadIdx.x;
    const int wid  = tid >> 5;
    const int lane = tid & 31;
    const int rowI = blockIdx.x * TILE;
    const int jtile0 = blockIdx.y * NJ;
    const int wrow = wid * 16;

    const int lrow = (lane & 7) + ((lane >> 3) & 1) * 8;
    const int lkof = (lane >> 4) * 16;

    const uint32_t aHiB = base + OFF_A_HI + (wrow + lrow) * PKB + lkof;
    const uint32_t aLoB = base + OFF_A_LO + (wrow + lrow) * PKB + lkof;

    // prologue: A hi/lo + B tile0 hi/lo in one cp.async group
    cp_tile(g_hi, rowI, base + OFF_A_HI, tid);
    cp_tile(g_lo, rowI, base + OFF_A_LO, tid);
    cp_tile(g_hi, jtile0 * TILE, base + OFF_B(0), tid);
    cp_tile(g_lo, jtile0 * TILE, base + OFF_B(0) + TB, tid);
    CP_COMMIT();

    float m0 = -INFINITY, s0 = 0.f;   // row wrow + lane/4      (log2 domain)
    float m1 = -INFINITY, s1 = 0.f;   // row wrow + lane/4 + 8

    for (int jt = 0; jt < NJ; jt++) {
        const int p = jt & 1, q = p ^ 1;
        const int jb = (jtile0 + jt) * TILE;

        CP_WAIT(0);
        __syncthreads();   // tile jt visible to all; all warps done with buf q

        if (jt + 1 < NJ) { // prefetch next tile into the just-freed buffer
            int jb2 = jb + TILE;
            cp_tile(g_hi, jb2, base + OFF_B(q), tid);
            cp_tile(g_lo, jb2, base + OFF_B(q) + TB, tid);
            CP_COMMIT();
        }

        // column-valid words for this tile (L1/L2-cached, broadcast)
        uint32_t vw0 = g_vmask[(jb >> 5) + 0];
        uint32_t vw1 = g_vmask[(jb >> 5) + 1];
        uint32_t vw2 = g_vmask[(jb >> 5) + 2];
        uint32_t vw3 = g_vmask[(jb >> 5) + 3];
        uint32_t vw[4] = {vw0, vw1, vw2, vw3};

        // ---- GEMM: acc = Ahi*Bhi^T + Alo*Bhi^T + Ahi*Blo^T ----
        float acc[16][4];
        #pragma unroll
        for (int nt = 0; nt < 16; nt++)
            #pragma unroll
            for (int c = 0; c < 4; c++) acc[nt][c] = 0.f;

        const uint32_t bHiB = base + OFF_B(p) + lrow * PKB + lkof;
        const uint32_t bLoB = bHiB + TB;

        #pragma unroll
        for (int ks = 0; ks < 8; ks++) {
            uint32_t aH[4], aL[4];
            ldsm4(aH, aHiB + ks * 32);
            ldsm4(aL, aLoB + ks * 32);
            #pragma unroll
            for (int nt2 = 0; nt2 < 8; nt2++) {
                uint32_t bH[4], bL[4];
                ldsm4(bH, bHiB + nt2 * (16 * PKB) + ks * 32);
                ldsm4(bL, bLoB + nt2 * (16 * PKB) + ks * 32);
                mma16816(acc[nt2 * 2 + 0], aH, bH[0], bH[2]);
                mma16816(acc[nt2 * 2 + 1], aH, bH[1], bH[3]);
                mma16816(acc[nt2 * 2 + 0], aL, bH[0], bH[2]);
                mma16816(acc[nt2 * 2 + 1], aL, bH[1], bH[3]);
                mma16816(acc[nt2 * 2 + 0], aH, bL[0], bL[2]);
                mma16816(acc[nt2 * 2 + 1], aH, bL[1], bL[3]);
            }
        }

        // ---- epilogue (registers only): masked online max + sum-exp2 ----
        float tm0 = -INFINITY, tm1 = -INFINITY;
        #pragma unroll
        for (int nt = 0; nt < 16; nt++) {
            int cn = nt * 8 + (lane & 3) * 2;
            uint32_t mk = (vw[nt >> 2] >> (cn & 31)) & 3u;
            float v0 = (mk & 1u) ? acc[nt][0] : -INFINITY;
            float v1 = (mk & 2u) ? acc[nt][1] : -INFINITY;
            float v2 = (mk & 1u) ? acc[nt][2] : -INFINITY;
            float v3 = (mk & 2u) ? acc[nt][3] : -INFINITY;
            acc[nt][0] = v0; acc[nt][1] = v1; acc[nt][2] = v2; acc[nt][3] = v3;
            tm0 = fmaxf(tm0, fmaxf(v0, v1));
            tm1 = fmaxf(tm1, fmaxf(v2, v3));
        }
        float ts0 = tm0 * SCALE_LOG2, ts1 = tm1 * SCALE_LOG2;
        if (ts0 > m0) { s0 *= ex2(m0 - ts0); m0 = ts0; }
        if (ts1 > m1) { s1 *= ex2(m1 - ts1); m1 = ts1; }
        if (m0 != -INFINITY) {
            float a0 = 0.f, a1 = 0.f;
            #pragma unroll
            for (int nt = 0; nt < 16; nt++) {
                a0 += ex2(fmaf(acc[nt][0], SCALE_LOG2, -m0));
                a1 += ex2(fmaf(acc[nt][1], SCALE_LOG2, -m0));
            }
            s0 += a0 + a1;
        }
        if (m1 != -INFINITY) {
            float a0 = 0.f, a1 = 0.f;
            #pragma unroll
            for (int nt = 0; nt < 16; nt++) {
                a0 += ex2(fmaf(acc[nt][2], SCALE_LOG2, -m1));
                a1 += ex2(fmaf(acc[nt][3], SCALE_LOG2, -m1));
            }
            s1 += a0 + a1;
        }
        // no trailing sync: next iteration's barrier covers buffer reuse
    }

    // combine across the 4 lanes of each quad (same output rows)
    #pragma unroll
    for (int off = 1; off <= 2; off <<= 1) {
        float mm = __shfl_xor_sync(0xffffffffu, m0, off);
        float ss = __shfl_xor_sync(0xffffffffu, s0, off);
        comb2(m0, s0, mm, ss);
        mm = __shfl_xor_sync(0xffffffffu, m1, off);
        ss = __shfl_xor_sync(0xffffffffu, s1, off);
        comb2(m1, s1, mm, ss);
    }
    if ((lane & 3) == 0) {
        int row = rowI + wrow + (lane >> 2);
        g_pm[blockIdx.y][row]     = m0;
        g_ps[blockIdx.y][row]     = s0;
        g_pm[blockIdx.y][row + 8] = m1;
        g_ps[blockIdx.y][row + 8] = s1;
    }
}

// ---------------------------------------------------------------------------
// Kernel 4: per-anchor finalize (combine partials, dot with G, block sums).
// ---------------------------------------------------------------------------
__global__ void fin_k(const float* __restrict__ f, const int* __restrict__ lw) {
    __shared__ float Gs[2 * D];
    __shared__ float red[256];
    int t = threadIdx.x;
    Gs[t] = ((const float*)g_G)[t];
    __syncthreads();

    int i = blockIdx.x * 256 + t;
    float M = g_pm[0][i], S = g_ps[0][i];
    comb2(M, S, g_pm[1][i], g_ps[1][i]);

    float term = 0.f;
    if (g_valid[i]) {
        float lse = (M + log2f(S)) * LN2F;    // back to natural units
        int lab = g_is64 ? lw[2 * i] : lw[i];
        const float4* fr = (const float4*)(f + (size_t)i * D);
        const float4* gr = (const float4*)(Gs + lab * D);
        float dot = 0.f;
        #pragma unroll
        for (int k = 0; k < D / 4; k++) {
            float4 a = fr[k]; float4 g = gr[k];
            dot = fmaf(a.x, g.x, dot); dot = fmaf(a.y, g.y, dot);
            dot = fmaf(a.z, g.z, dot); dot = fmaf(a.w, g.w, dot);
        }
        float cnt = (float)g_C[lab];
        term = (cnt * lse - dot * TEMP_INV) * (1.0f / 128.0f);
    }
    red[t] = term;
    __syncthreads();
    for (int st = 128; st > 0; st >>= 1) {
        if (t < st) red[t] += red[t + st];
        __syncthreads();
    }
    if (t == 0) g_bsum[blockIdx.x] = red[0];
}

__global__ void fin2_k(float* out) {
    if (threadIdx.x == 0) {
        float s = 0.f;
        for (int i = 0; i < FIN_BLOCKS; i++) s += g_bsum[i];
        out[0] = s * (1.0f / 256.0f);
    }
}

// ---------------------------------------------------------------------------
extern "C" void kernel_launch(void* const* d_in, const int* in_sizes, int n_in,
                              void* d_out, int out_size) {
    const float* f  = (const float*)d_in[0];
    const int*   lw = (const int*)d_in[1];
    float* out = (float*)d_out;

    cudaFuncSetAttribute(lse_mma_k, cudaFuncAttributeMaxDynamicSharedMemorySize, SMEM_BYTES);

    init_detect_k<<<1, 256>>>(lw);
    cvt_k<<<N_TOT, 128>>>(f);
    vmask_k<<<N_TOT / 256, 256>>>();
    prep_k<<<NI, 128>>>(f, lw);
    lse_mma_k<<<dim3(NI, NJG), 256, SMEM_BYTES>>>();
    fin_k<<<FIN_BLOCKS, 256>>>(f, lw);
    fin2_k<<<1, 32>>>(out);
}

// round 6
// speedup vs baseline: 2.5514x; 1.1157x over previous
#include <cuda_runtime.h>
#include <cuda_bf16.h>
#include <math.h>
#include <stdint.h>

// ---------------------------------------------------------------------------
// Problem constants
// ---------------------------------------------------------------------------
#define N_TOT 8192
#define D 128
#define TEMP_INV (1.0f/0.07f)
#define SCALE_LOG2 (1.44269504088896340736f/0.07f)   /* log2(e)/T */
#define LN2F 0.6931471805599453f
#define TILE 128
#define NI 64          /* I tiles */
#define NJG 2          /* J groups (grid.y) */
#define NJ 32          /* J tiles per CTA */
#define FIN_BLOCKS 128

// SMEM tile geometry: 128 rows x 128 bf16, padded row stride 136 elem (272 B)
#define PKB 272
#define TB  (128 * PKB)
#define OFF_A_HI 0
#define OFF_A_LO TB
#define OFF_B(b) (2*TB + (b)*(2*TB))   /* hi at +0, lo at +TB */
#define SMEM_BYTES (6*TB)              /* 208896 */

// ---------------------------------------------------------------------------
// Device scratch
// ---------------------------------------------------------------------------
__device__ __nv_bfloat16 g_hi[N_TOT * D];
__device__ __nv_bfloat16 g_lo[N_TOT * D];
__device__ float    g_G[2][D];
__device__ int      g_C[2];
__device__ int      g_valid[N_TOT];
__device__ int      g_cls[N_TOT];       /* 0 = invalid, 1 = class0, 2 = class1 */
__device__ uint32_t g_vmask[N_TOT / 32];
__device__ float    g_pm[NJG][N_TOT];   /* log2-domain running max */
__device__ float    g_ps[NJG][N_TOT];
__device__ float    g_bsum[FIN_BLOCKS];
__device__ int      g_is64;

// ---------------------------------------------------------------------------
// Family-safe PTX helpers
// ---------------------------------------------------------------------------
__device__ __forceinline__ uint32_t smem_u32(const void* p) {
    uint32_t a;
    asm("{ .reg .u64 t; cvta.to.shared.u64 t, %1; cvt.u32.u64 %0, t; }" : "=r"(a) : "l"(p));
    return a;
}
__device__ __forceinline__ void ldsm4(uint32_t* r, uint32_t addr) {
    asm volatile("ldmatrix.sync.aligned.m8n8.x4.shared.b16 {%0,%1,%2,%3}, [%4];"
                 : "=r"(r[0]), "=r"(r[1]), "=r"(r[2]), "=r"(r[3]) : "r"(addr));
}
__device__ __forceinline__ void mma16816(float* c, const uint32_t* a, uint32_t b0, uint32_t b1) {
    asm volatile("mma.sync.aligned.m16n8k16.row.col.f32.bf16.bf16.f32 "
                 "{%0,%1,%2,%3}, {%4,%5,%6,%7}, {%8,%9}, {%0,%1,%2,%3};"
                 : "+f"(c[0]), "+f"(c[1]), "+f"(c[2]), "+f"(c[3])
                 : "r"(a[0]), "r"(a[1]), "r"(a[2]), "r"(a[3]), "r"(b0), "r"(b1));
}
__device__ __forceinline__ void cp16(uint32_t dst, const void* src) {
    asm volatile("cp.async.cg.shared.global [%0], [%1], 16;" :: "r"(dst), "l"(src));
}
#define CP_COMMIT() asm volatile("cp.async.commit_group;" ::: "memory")
#define CP_WAIT(n)  asm volatile("cp.async.wait_group %0;" :: "n"(n) : "memory")

__device__ __forceinline__ float ex2(float x) {
    float y;
    asm("ex2.approx.ftz.f32 %0, %1;" : "=f"(y) : "f"(x));
    return y;
}

// online-softmax merge, log2 domain
__device__ __forceinline__ void comb2(float& m, float& s, float m2, float s2) {
    float M = fmaxf(m, m2);
    float S;
    if (M == -INFINITY) S = 0.f;
    else S = ((m  == -INFINITY) ? 0.f : s  * ex2(m  - M))
           + ((m2 == -INFINITY) ? 0.f : s2 * ex2(m2 - M));
    m = M; s = S;
}

__device__ __forceinline__ void cp_tile(const __nv_bfloat16* __restrict__ src, int rowBase,
                                        uint32_t dstBase, int tid) {
    #pragma unroll
    for (int it = 0; it < 8; ++it) {
        int i = tid + it * 256;
        int row = i >> 4, c = i & 15;
        cp16(dstBase + row * PKB + c * 16, src + (size_t)(rowBase + row) * D + c * 8);
    }
}

// ---------------------------------------------------------------------------
// Kernel 0: zero class sums/counts + detect int64 vs int32 labels.
// ---------------------------------------------------------------------------
__global__ void init_detect_k(const int* __restrict__ lw) {
    int t = threadIdx.x;
    if (t < 2 * D) ((float*)g_G)[t] = 0.0f;
    if (t < 2)     g_C[t] = 0;
    int local = 0;
    for (int i = 1 + 2 * t; i < N_TOT; i += 2 * 256) local |= lw[i];
    __shared__ int anynz;
    if (t == 0) anynz = 0;
    __syncthreads();
    if (local) atomicOr(&anynz, 1);
    __syncthreads();
    if (t == 0) g_is64 = anynz ? 0 : 1;
}

// ---------------------------------------------------------------------------
// Kernel 1: bf16 hi/lo split + valid flag + class code. 128 threads per row.
// ---------------------------------------------------------------------------
__global__ void cvt_k(const float* __restrict__ f, const int* __restrict__ lw) {
    int row = blockIdx.x, k = threadIdx.x;
    size_t i = (size_t)row * D + k;
    float v = f[i];
    __nv_bfloat16 h = __float2bfloat16(v);
    g_hi[i] = h;
    g_lo[i] = __float2bfloat16(v - __bfloat162float(h));
    int nz = __syncthreads_or(v != 0.0f);
    if (k == 0) {
        g_valid[row] = nz;
        int lab = g_is64 ? lw[2 * row] : lw[row];
        g_cls[row] = nz ? (lab + 1) : 0;
    }
}

// Kernel 1b: pack valid flags into bitmask words.
__global__ void vmask_k() {
    int i = blockIdx.x * 256 + threadIdx.x;
    uint32_t b = __ballot_sync(0xffffffffu, g_valid[i] != 0);
    if ((threadIdx.x & 31) == 0) g_vmask[i >> 5] = b;
}

// ---------------------------------------------------------------------------
// Kernel 2: per-class feature sums/counts. 128 blocks x 128 thr, 64 rows each.
// Branchless select-accumulate, unrolled for MLP; single atomic pair per thread.
// ---------------------------------------------------------------------------
__global__ void prep_k(const float* __restrict__ f) {
    const int k  = threadIdx.x;
    const int r0 = blockIdx.x * 64;
    float a0 = 0.f, a1 = 0.f;
    #pragma unroll 8
    for (int r = 0; r < 64; r++) {
        int cls = g_cls[r0 + r];                 // uniform broadcast load
        float v = f[(size_t)(r0 + r) * D + k];
        a0 += (cls == 1) ? v : 0.0f;
        a1 += (cls == 2) ? v : 0.0f;
    }
    atomicAdd(&g_G[0][k], a0);
    atomicAdd(&g_G[1][k], a1);

    // counts: threads 0..63 examine one row each (2 warps, ballot+popc)
    if (k < 64) {
        int cls = g_cls[r0 + k];
        uint32_t b1 = __ballot_sync(0xffffffffu, cls == 1);
        uint32_t b2 = __ballot_sync(0xffffffffu, cls == 2);
        if ((k & 31) == 0) {
            atomicAdd(&g_C[0], __popc(b1));
            atomicAdd(&g_C[1], __popc(b2));
        }
    }
}

// ---------------------------------------------------------------------------
// Kernel 3: bf16-split GEMM (HMMA) + fused online logsumexp (log2 domain).
// grid (NI, NJG), 256 threads. One __syncthreads per J-tile; epilogue is
// register-only and overlaps the next tile's cp.async. (unchanged from R5)
// ---------------------------------------------------------------------------
__global__ void __launch_bounds__(256, 1) lse_mma_k() {
    extern __shared__ char smc[];
    const uint32_t base = smem_u32(smc);

    const int tid  = threadIdx.x;
    const int wid  = tid >> 5;
    const int lane = tid & 31;
    const int rowI = blockIdx.x * TILE;
    const int jtile0 = blockIdx.y * NJ;
    const int wrow = wid * 16;

    const int lrow = (lane & 7) + ((lane >> 3) & 1) * 8;
    const int lkof = (lane >> 4) * 16;

    const uint32_t aHiB = base + OFF_A_HI + (wrow + lrow) * PKB + lkof;
    const uint32_t aLoB = base + OFF_A_LO + (wrow + lrow) * PKB + lkof;

    cp_tile(g_hi, rowI, base + OFF_A_HI, tid);
    cp_tile(g_lo, rowI, base + OFF_A_LO, tid);
    cp_tile(g_hi, jtile0 * TILE, base + OFF_B(0), tid);
    cp_tile(g_lo, jtile0 * TILE, base + OFF_B(0) + TB, tid);
    CP_COMMIT();

    float m0 = -INFINITY, s0 = 0.f;
    float m1 = -INFINITY, s1 = 0.f;

    for (int jt = 0; jt < NJ; jt++) {
        const int p = jt & 1, q = p ^ 1;
        const int jb = (jtile0 + jt) * TILE;

        CP_WAIT(0);
        __syncthreads();

        if (jt + 1 < NJ) {
            int jb2 = jb + TILE;
            cp_tile(g_hi, jb2, base + OFF_B(q), tid);
            cp_tile(g_lo, jb2, base + OFF_B(q) + TB, tid);
            CP_COMMIT();
        }

        uint32_t vw0 = g_vmask[(jb >> 5) + 0];
        uint32_t vw1 = g_vmask[(jb >> 5) + 1];
        uint32_t vw2 = g_vmask[(jb >> 5) + 2];
        uint32_t vw3 = g_vmask[(jb >> 5) + 3];
        uint32_t vw[4] = {vw0, vw1, vw2, vw3};

        float acc[16][4];
        #pragma unroll
        for (int nt = 0; nt < 16; nt++)
            #pragma unroll
            for (int c = 0; c < 4; c++) acc[nt][c] = 0.f;

        const uint32_t bHiB = base + OFF_B(p) + lrow * PKB + lkof;
        const uint32_t bLoB = bHiB + TB;

        #pragma unroll
        for (int ks = 0; ks < 8; ks++) {
            uint32_t aH[4], aL[4];
            ldsm4(aH, aHiB + ks * 32);
            ldsm4(aL, aLoB + ks * 32);
            #pragma unroll
            for (int nt2 = 0; nt2 < 8; nt2++) {
                uint32_t bH[4], bL[4];
                ldsm4(bH, bHiB + nt2 * (16 * PKB) + ks * 32);
                ldsm4(bL, bLoB + nt2 * (16 * PKB) + ks * 32);
                mma16816(acc[nt2 * 2 + 0], aH, bH[0], bH[2]);
                mma16816(acc[nt2 * 2 + 1], aH, bH[1], bH[3]);
                mma16816(acc[nt2 * 2 + 0], aL, bH[0], bH[2]);
                mma16816(acc[nt2 * 2 + 1], aL, bH[1], bH[3]);
                mma16816(acc[nt2 * 2 + 0], aH, bL[0], bL[2]);
                mma16816(acc[nt2 * 2 + 1], aH, bL[1], bL[3]);
            }
        }

        float tm0 = -INFINITY, tm1 = -INFINITY;
        #pragma unroll
        for (int nt = 0; nt < 16; nt++) {
            int cn = nt * 8 + (lane & 3) * 2;
            uint32_t mk = (vw[nt >> 2] >> (cn & 31)) & 3u;
            float v0 = (mk & 1u) ? acc[nt][0] : -INFINITY;
            float v1 = (mk & 2u) ? acc[nt][1] : -INFINITY;
            float v2 = (mk & 1u) ? acc[nt][2] : -INFINITY;
            float v3 = (mk & 2u) ? acc[nt][3] : -INFINITY;
            acc[nt][0] = v0; acc[nt][1] = v1; acc[nt][2] = v2; acc[nt][3] = v3;
            tm0 = fmaxf(tm0, fmaxf(v0, v1));
            tm1 = fmaxf(tm1, fmaxf(v2, v3));
        }
        float ts0 = tm0 * SCALE_LOG2, ts1 = tm1 * SCALE_LOG2;
        if (ts0 > m0) { s0 *= ex2(m0 - ts0); m0 = ts0; }
        if (ts1 > m1) { s1 *= ex2(m1 - ts1); m1 = ts1; }
        if (m0 != -INFINITY) {
            float a0 = 0.f, a1 = 0.f;
            #pragma unroll
            for (int nt = 0; nt < 16; nt++) {
                a0 += ex2(fmaf(acc[nt][0], SCALE_LOG2, -m0));
                a1 += ex2(fmaf(acc[nt][1], SCALE_LOG2, -m0));
            }
            s0 += a0 + a1;
        }
        if (m1 != -INFINITY) {
            float a0 = 0.f, a1 = 0.f;
            #pragma unroll
            for (int nt = 0; nt < 16; nt++) {
                a0 += ex2(fmaf(acc[nt][2], SCALE_LOG2, -m1));
                a1 += ex2(fmaf(acc[nt][3], SCALE_LOG2, -m1));
            }
            s1 += a0 + a1;
        }
    }

    #pragma unroll
    for (int off = 1; off <= 2; off <<= 1) {
        float mm = __shfl_xor_sync(0xffffffffu, m0, off);
        float ss = __shfl_xor_sync(0xffffffffu, s0, off);
        comb2(m0, s0, mm, ss);
        mm = __shfl_xor_sync(0xffffffffu, m1, off);
        ss = __shfl_xor_sync(0xffffffffu, s1, off);
        comb2(m1, s1, mm, ss);
    }
    if ((lane & 3) == 0) {
        int row = rowI + wrow + (lane >> 2);
        g_pm[blockIdx.y][row]     = m0;
        g_ps[blockIdx.y][row]     = s0;
        g_pm[blockIdx.y][row + 8] = m1;
        g_ps[blockIdx.y][row + 8] = s1;
    }
}

// ---------------------------------------------------------------------------
// Kernel 4: per-anchor finalize. 4 threads per anchor (quad-split dot, shfl
// combine) -> 32K threads for load parallelism. 128 blocks x 256 threads.
// ---------------------------------------------------------------------------
__global__ void fin_k(const float* __restrict__ f) {
    __shared__ float Gs[2 * D];
    __shared__ float red[64];
    const int t = threadIdx.x;
    if (t < 2 * D) Gs[t] = ((const float*)g_G)[t];
    __syncthreads();

    const int aIdx = t >> 2;                 // anchor within block (0..63)
    const int qt   = t & 3;                  // quad thread
    const int i    = blockIdx.x * 64 + aIdx; // global anchor

    int cls = g_cls[i];
    float term = 0.f;

    // quad-split dot: thread qt covers elements [qt*32, qt*32+32)
    float dot = 0.f;
    {
        int lab = (cls == 2) ? 1 : 0;
        const float4* fr = (const float4*)(f + (size_t)i * D) + qt * 8;
        const float4* gr = (const float4*)(Gs + lab * D) + qt * 8;
        #pragma unroll
        for (int k = 0; k < 8; k++) {
            float4 a = fr[k]; float4 g = gr[k];
            dot = fmaf(a.x, g.x, dot); dot = fmaf(a.y, g.y, dot);
            dot = fmaf(a.z, g.z, dot); dot = fmaf(a.w, g.w, dot);
        }
    }
    dot += __shfl_xor_sync(0xffffffffu, dot, 1);
    dot += __shfl_xor_sync(0xffffffffu, dot, 2);

    if (qt == 0 && cls != 0) {
        float M = g_pm[0][i], S = g_ps[0][i];
        comb2(M, S, g_pm[1][i], g_ps[1][i]);
        float lse = (M + log2f(S)) * LN2F;
        float cnt = (float)g_C[(cls == 2) ? 1 : 0];
        term = (cnt * lse - dot * TEMP_INV) * (1.0f / 128.0f);
    }

    // block reduction over the 64 quad leaders
    if (qt == 0) red[aIdx] = term;
    __syncthreads();
    if (t < 32) {
        float v = red[t] + red[t + 32];
        #pragma unroll
        for (int off = 16; off > 0; off >>= 1)
            v += __shfl_xor_sync(0xffffffffu, v, off);
        if (t == 0) g_bsum[blockIdx.x] = v;
    }
}

__global__ void fin2_k(float* out) {
    int t = threadIdx.x;             // 128 threads
    float v = g_bsum[t];
    #pragma unroll
    for (int off = 16; off > 0; off >>= 1)
        v += __shfl_xor_sync(0xffffffffu, v, off);
    __shared__ float ws[4];
    if ((t & 31) == 0) ws[t >> 5] = v;
    __syncthreads();
    if (t == 0) out[0] = (ws[0] + ws[1] + ws[2] + ws[3]) * (1.0f / 256.0f);
}

// ---------------------------------------------------------------------------
extern "C" void kernel_launch(void* const* d_in, const int* in_sizes, int n_in,
                              void* d_out, int out_size) {
    const float* f  = (const float*)d_in[0];
    const int*   lw = (const int*)d_in[1];
    float* out = (float*)d_out;

    cudaFuncSetAttribute(lse_mma_k, cudaFuncAttributeMaxDynamicSharedMemorySize, SMEM_BYTES);

    init_detect_k<<<1, 256>>>(lw);
    cvt_k<<<N_TOT, 128>>>(f, lw);
    vmask_k<<<N_TOT / 256, 256>>>();
    prep_k<<<128, 128>>>(f);
    lse_mma_k<<<dim3(NI, NJG), 256, SMEM_BYTES>>>();
    fin_k<<<FIN_BLOCKS, 256>>>(f);
    fin2_k<<<1, 128>>>(out);
}

// round 7
// speedup vs baseline: 2.8497x; 1.1169x over previous
#include <cuda_runtime.h>
#include <cuda_bf16.h>
#include <math.h>
#include <stdint.h>

// ---------------------------------------------------------------------------
// Problem constants
// ---------------------------------------------------------------------------
#define N_TOT 8192
#define D 128
#define TEMP_INV (1.0f/0.07f)
#define SCALE_LOG2 (1.44269504088896340736f/0.07f)   /* log2(e)/T */
#define LN2F 0.6931471805599453f
#define TILE 128
#define NCTA 152            /* GB300 has 152 SMs */
#define NUNITS 1024         /* 64 I-tiles x 16 J-chunks (4 tiles each) */
#define NSLOT 4             /* max partial-writers per I-block */
#define FIN_BLOCKS 128

// SMEM tile geometry: 128 rows x 128 bf16, padded row stride 136 elem (272 B)
#define PKB 272
#define TB  (128 * PKB)
#define OFF_A_HI 0
#define OFF_A_LO TB
#define OFF_B(b) (2*TB + (b)*(2*TB))   /* hi at +0, lo at +TB */
#define SMEM_BYTES (6*TB)              /* 208896 */

// ---------------------------------------------------------------------------
// Device scratch
// ---------------------------------------------------------------------------
__device__ __nv_bfloat16 g_hi[N_TOT * D];
__device__ __nv_bfloat16 g_lo[N_TOT * D];
__device__ float    g_G[2][D];
__device__ int      g_C[2];
__device__ int      g_valid[N_TOT];
__device__ int      g_cls[N_TOT];       /* 0 = invalid, 1 = class0, 2 = class1 */
__device__ uint32_t g_vmask[N_TOT / 32];
__device__ float    g_pm[NSLOT][N_TOT]; /* log2-domain running max partials */
__device__ float    g_ps[NSLOT][N_TOT];
__device__ float    g_bsum[FIN_BLOCKS];
__device__ int      g_is64;

// ---------------------------------------------------------------------------
// Family-safe PTX helpers
// ---------------------------------------------------------------------------
__device__ __forceinline__ uint32_t smem_u32(const void* p) {
    uint32_t a;
    asm("{ .reg .u64 t; cvta.to.shared.u64 t, %1; cvt.u32.u64 %0, t; }" : "=r"(a) : "l"(p));
    return a;
}
__device__ __forceinline__ void ldsm4(uint32_t* r, uint32_t addr) {
    asm volatile("ldmatrix.sync.aligned.m8n8.x4.shared.b16 {%0,%1,%2,%3}, [%4];"
                 : "=r"(r[0]), "=r"(r[1]), "=r"(r[2]), "=r"(r[3]) : "r"(addr));
}
__device__ __forceinline__ void mma16816(float* c, const uint32_t* a, uint32_t b0, uint32_t b1) {
    asm volatile("mma.sync.aligned.m16n8k16.row.col.f32.bf16.bf16.f32 "
                 "{%0,%1,%2,%3}, {%4,%5,%6,%7}, {%8,%9}, {%0,%1,%2,%3};"
                 : "+f"(c[0]), "+f"(c[1]), "+f"(c[2]), "+f"(c[3])
                 : "r"(a[0]), "r"(a[1]), "r"(a[2]), "r"(a[3]), "r"(b0), "r"(b1));
}
__device__ __forceinline__ void cp16(uint32_t dst, const void* src) {
    asm volatile("cp.async.cg.shared.global [%0], [%1], 16;" :: "r"(dst), "l"(src));
}
#define CP_COMMIT() asm volatile("cp.async.commit_group;" ::: "memory")
#define CP_WAIT(n)  asm volatile("cp.async.wait_group %0;" :: "n"(n) : "memory")

__device__ __forceinline__ float ex2(float x) {
    float y;
    asm("ex2.approx.ftz.f32 %0, %1;" : "=f"(y) : "f"(x));
    return y;
}

// online-softmax merge, log2 domain
__device__ __forceinline__ void comb2(float& m, float& s, float m2, float s2) {
    float M = fmaxf(m, m2);
    float S;
    if (M == -INFINITY) S = 0.f;
    else S = ((m  == -INFINITY) ? 0.f : s  * ex2(m  - M))
           + ((m2 == -INFINITY) ? 0.f : s2 * ex2(m2 - M));
    m = M; s = S;
}

__device__ __forceinline__ void cp_tile(const __nv_bfloat16* __restrict__ src, int rowBase,
                                        uint32_t dstBase, int tid) {
    #pragma unroll
    for (int it = 0; it < 8; ++it) {
        int i = tid + it * 256;
        int row = i >> 4, c = i & 15;
        cp16(dstBase + row * PKB + c * 16, src + (size_t)(rowBase + row) * D + c * 8);
    }
}

// ---------------------------------------------------------------------------
// Kernel 0: zero class sums/counts + detect int64 vs int32 labels.
// ---------------------------------------------------------------------------
__global__ void init_detect_k(const int* __restrict__ lw) {
    int t = threadIdx.x;
    if (t < 2 * D) ((float*)g_G)[t] = 0.0f;
    if (t < 2)     g_C[t] = 0;
    int local = 0;
    for (int i = 1 + 2 * t; i < N_TOT; i += 2 * 256) local |= lw[i];
    __shared__ int anynz;
    if (t == 0) anynz = 0;
    __syncthreads();
    if (local) atomicOr(&anynz, 1);
    __syncthreads();
    if (t == 0) g_is64 = anynz ? 0 : 1;
}

// ---------------------------------------------------------------------------
// Kernel 1: bf16 hi/lo split + valid flag + class code. 128 threads per row.
// ---------------------------------------------------------------------------
__global__ void cvt_k(const float* __restrict__ f, const int* __restrict__ lw) {
    int row = blockIdx.x, k = threadIdx.x;
    size_t i = (size_t)row * D + k;
    float v = f[i];
    __nv_bfloat16 h = __float2bfloat16(v);
    g_hi[i] = h;
    g_lo[i] = __float2bfloat16(v - __bfloat162float(h));
    int nz = __syncthreads_or(v != 0.0f);
    if (k == 0) {
        g_valid[row] = nz;
        int lab = g_is64 ? lw[2 * row] : lw[row];
        g_cls[row] = nz ? (lab + 1) : 0;
    }
}

// Kernel 1b: pack valid bitmask + init partial slots.
__global__ void vmask_k() {
    int i = blockIdx.x * 256 + threadIdx.x;
    uint32_t b = __ballot_sync(0xffffffffu, g_valid[i] != 0);
    if ((threadIdx.x & 31) == 0) g_vmask[i >> 5] = b;
    #pragma unroll
    for (int s = 0; s < NSLOT; s++) { g_pm[s][i] = -INFINITY; g_ps[s][i] = 0.f; }
}

// ---------------------------------------------------------------------------
// Kernel 2: per-class feature sums/counts. 256 blocks x 128 thr, 32 rows each.
// ---------------------------------------------------------------------------
__global__ void prep_k(const float* __restrict__ f) {
    const int k  = threadIdx.x;
    const int r0 = blockIdx.x * 32;
    float a0 = 0.f, a1 = 0.f;
    #pragma unroll 8
    for (int r = 0; r < 32; r++) {
        int cls = g_cls[r0 + r];
        float v = f[(size_t)(r0 + r) * D + k];
        a0 += (cls == 1) ? v : 0.0f;
        a1 += (cls == 2) ? v : 0.0f;
    }
    atomicAdd(&g_G[0][k], a0);
    atomicAdd(&g_G[1][k], a1);

    if (k < 32) {
        int cls = g_cls[r0 + k];
        uint32_t b1 = __ballot_sync(0xffffffffu, cls == 1);
        uint32_t b2 = __ballot_sync(0xffffffffu, cls == 2);
        if (k == 0) {
            atomicAdd(&g_C[0], __popc(b1));
            atomicAdd(&g_C[1], __popc(b2));
        }
    }
}

// ---------------------------------------------------------------------------
// Kernel 3: bf16-split GEMM (HMMA) + fused online logsumexp (log2 domain).
// 152 CTAs, statically balanced: 1024 units of (I-tile, 4 J-tiles) split
// contiguously (I-major) -> 6..7 units/CTA, <=2 segments, <=1 A reload.
// Partials land in slot = ceil(offset_in_I_block / 6)  (<=4 distinct per I).
// ---------------------------------------------------------------------------
__global__ void __launch_bounds__(256, 1) lse_mma_k() {
    extern __shared__ char smc[];
    const uint32_t base = smem_u32(smc);

    const int tid  = threadIdx.x;
    const int wid  = tid >> 5;
    const int lane = tid & 31;
    const int wrow = wid * 16;
    const int lrow = (lane & 7) + ((lane >> 3) & 1) * 8;
    const int lkof = (lane >> 4) * 16;

    // static unit range for this CTA
    const int c  = blockIdx.x;
    const int u0 = (c * NUNITS) / NCTA;
    const int u1 = ((c + 1) * NUNITS) / NCTA;

    int nseg, sI[2], sJA[2], sJB[2], sSl[2];
    {
        int I0 = u0 >> 4, bnd = (I0 + 1) << 4;
        int e1 = (u1 < bnd) ? u1 : bnd;
        sI[0] = I0;
        sJA[0] = (u0 & 15) * 4;
        sJB[0] = sJA[0] + (e1 - u0) * 4;
        sSl[0] = ((u0 & 15) + 5) / 6;
        if (u1 > bnd) { sI[1] = I0 + 1; sJA[1] = 0; sJB[1] = (u1 - bnd) * 4; sSl[1] = 0; nseg = 2; }
        else nseg = 1;
    }

    const uint32_t aHiB = base + OFF_A_HI + (wrow + lrow) * PKB + lkof;
    const uint32_t aLoB = base + OFF_A_LO + (wrow + lrow) * PKB + lkof;

    for (int g = 0; g < nseg; g++) {
        const int rowI = sI[g] * TILE;
        const int jA = sJA[g], jB = sJB[g];

        // segment prologue: A hi/lo + first B tile
        cp_tile(g_hi, rowI, base + OFF_A_HI, tid);
        cp_tile(g_lo, rowI, base + OFF_A_LO, tid);
        cp_tile(g_hi, jA * TILE, base + OFF_B(0), tid);
        cp_tile(g_lo, jA * TILE, base + OFF_B(0) + TB, tid);
        CP_COMMIT();

        float m0 = -INFINITY, s0 = 0.f;
        float m1 = -INFINITY, s1 = 0.f;

        for (int jt = jA; jt < jB; jt++) {
            const int p = (jt - jA) & 1, q = p ^ 1;
            const int jb = jt * TILE;

            CP_WAIT(0);
            __syncthreads();

            if (jt + 1 < jB) {
                int jb2 = jb + TILE;
                cp_tile(g_hi, jb2, base + OFF_B(q), tid);
                cp_tile(g_lo, jb2, base + OFF_B(q) + TB, tid);
                CP_COMMIT();
            }

            uint32_t vw[4];
            vw[0] = g_vmask[(jb >> 5) + 0];
            vw[1] = g_vmask[(jb >> 5) + 1];
            vw[2] = g_vmask[(jb >> 5) + 2];
            vw[3] = g_vmask[(jb >> 5) + 3];

            float acc[16][4];
            #pragma unroll
            for (int nt = 0; nt < 16; nt++)
                #pragma unroll
                for (int cc = 0; cc < 4; cc++) acc[nt][cc] = 0.f;

            const uint32_t bHiB = base + OFF_B(p) + lrow * PKB + lkof;
            const uint32_t bLoB = bHiB + TB;

            #pragma unroll
            for (int ks = 0; ks < 8; ks++) {
                uint32_t aH[4], aL[4];
                ldsm4(aH, aHiB + ks * 32);
                ldsm4(aL, aLoB + ks * 32);
                #pragma unroll
                for (int nt2 = 0; nt2 < 8; nt2++) {
                    uint32_t bH[4], bL[4];
                    ldsm4(bH, bHiB + nt2 * (16 * PKB) + ks * 32);
                    ldsm4(bL, bLoB + nt2 * (16 * PKB) + ks * 32);
                    mma16816(acc[nt2 * 2 + 0], aH, bH[0], bH[2]);
                    mma16816(acc[nt2 * 2 + 1], aH, bH[1], bH[3]);
                    mma16816(acc[nt2 * 2 + 0], aL, bH[0], bH[2]);
                    mma16816(acc[nt2 * 2 + 1], aL, bH[1], bH[3]);
                    mma16816(acc[nt2 * 2 + 0], aH, bL[0], bL[2]);
                    mma16816(acc[nt2 * 2 + 1], aH, bL[1], bL[3]);
                }
            }

            float tm0 = -INFINITY, tm1 = -INFINITY;
            #pragma unroll
            for (int nt = 0; nt < 16; nt++) {
                int cn = nt * 8 + (lane & 3) * 2;
                uint32_t mk = (vw[nt >> 2] >> (cn & 31)) & 3u;
                float v0 = (mk & 1u) ? acc[nt][0] : -INFINITY;
                float v1 = (mk & 2u) ? acc[nt][1] : -INFINITY;
                float v2 = (mk & 1u) ? acc[nt][2] : -INFINITY;
                float v3 = (mk & 2u) ? acc[nt][3] : -INFINITY;
                acc[nt][0] = v0; acc[nt][1] = v1; acc[nt][2] = v2; acc[nt][3] = v3;
                tm0 = fmaxf(tm0, fmaxf(v0, v1));
                tm1 = fmaxf(tm1, fmaxf(v2, v3));
            }
            float ts0 = tm0 * SCALE_LOG2, ts1 = tm1 * SCALE_LOG2;
            if (ts0 > m0) { s0 *= ex2(m0 - ts0); m0 = ts0; }
            if (ts1 > m1) { s1 *= ex2(m1 - ts1); m1 = ts1; }
            if (m0 != -INFINITY) {
                float a0 = 0.f, a1 = 0.f;
                #pragma unroll
                for (int nt = 0; nt < 16; nt++) {
                    a0 += ex2(fmaf(acc[nt][0], SCALE_LOG2, -m0));
                    a1 += ex2(fmaf(acc[nt][1], SCALE_LOG2, -m0));
                }
                s0 += a0 + a1;
            }
            if (m1 != -INFINITY) {
                float a0 = 0.f, a1 = 0.f;
                #pragma unroll
                for (int nt = 0; nt < 16; nt++) {
                    a0 += ex2(fmaf(acc[nt][2], SCALE_LOG2, -m1));
                    a1 += ex2(fmaf(acc[nt][3], SCALE_LOG2, -m1));
                }
                s1 += a0 + a1;
            }
        }

        // quad combine + write this segment's partial into its slot
        #pragma unroll
        for (int off = 1; off <= 2; off <<= 1) {
            float mm = __shfl_xor_sync(0xffffffffu, m0, off);
            float ss = __shfl_xor_sync(0xffffffffu, s0, off);
            comb2(m0, s0, mm, ss);
            mm = __shfl_xor_sync(0xffffffffu, m1, off);
            ss = __shfl_xor_sync(0xffffffffu, s1, off);
            comb2(m1, s1, mm, ss);
        }
        if ((lane & 3) == 0) {
            int row = rowI + wrow + (lane >> 2);
            int sl = sSl[g];
            g_pm[sl][row]     = m0;
            g_ps[sl][row]     = s0;
            g_pm[sl][row + 8] = m1;
            g_ps[sl][row + 8] = s1;
        }
        __syncthreads();   // all warps done with buffers before next segment's prologue
    }
}

// ---------------------------------------------------------------------------
// Kernel 4: per-anchor finalize. 4 threads per anchor; combine NSLOT partials.
// ---------------------------------------------------------------------------
__global__ void fin_k(const float* __restrict__ f) {
    __shared__ float Gs[2 * D];
    __shared__ float red[64];
    const int t = threadIdx.x;
    if (t < 2 * D) Gs[t] = ((const float*)g_G)[t];
    __syncthreads();

    const int aIdx = t >> 2;
    const int qt   = t & 3;
    const int i    = blockIdx.x * 64 + aIdx;

    int cls = g_cls[i];
    float term = 0.f;

    float dot = 0.f;
    {
        int lab = (cls == 2) ? 1 : 0;
        const float4* fr = (const float4*)(f + (size_t)i * D) + qt * 8;
        const float4* gr = (const float4*)(Gs + lab * D) + qt * 8;
        #pragma unroll
        for (int k = 0; k < 8; k++) {
            float4 a = fr[k]; float4 g = gr[k];
            dot = fmaf(a.x, g.x, dot); dot = fmaf(a.y, g.y, dot);
            dot = fmaf(a.z, g.z, dot); dot = fmaf(a.w, g.w, dot);
        }
    }
    dot += __shfl_xor_sync(0xffffffffu, dot, 1);
    dot += __shfl_xor_sync(0xffffffffu, dot, 2);

    if (qt == 0 && cls != 0) {
        float M = g_pm[0][i], S = g_ps[0][i];
        comb2(M, S, g_pm[1][i], g_ps[1][i]);
        comb2(M, S, g_pm[2][i], g_ps[2][i]);
        comb2(M, S, g_pm[3][i], g_ps[3][i]);
        float lse = (M + log2f(S)) * LN2F;
        float cnt = (float)g_C[(cls == 2) ? 1 : 0];
        term = (cnt * lse - dot * TEMP_INV) * (1.0f / 128.0f);
    }

    if (qt == 0) red[aIdx] = term;
    __syncthreads();
    if (t < 32) {
        float v = red[t] + red[t + 32];
        #pragma unroll
        for (int off = 16; off > 0; off >>= 1)
            v += __shfl_xor_sync(0xffffffffu, v, off);
        if (t == 0) g_bsum[blockIdx.x] = v;
    }
}

__global__ void fin2_k(float* out) {
    int t = threadIdx.x;             // 128 threads
    float v = g_bsum[t];
    #pragma unroll
    for (int off = 16; off > 0; off >>= 1)
        v += __shfl_xor_sync(0xffffffffu, v, off);
    __shared__ float ws[4];
    if ((t & 31) == 0) ws[t >> 5] = v;
    __syncthreads();
    if (t == 0) out[0] = (ws[0] + ws[1] + ws[2] + ws[3]) * (1.0f / 256.0f);
}

// ---------------------------------------------------------------------------
extern "C" void kernel_launch(void* const* d_in, const int* in_sizes, int n_in,
                              void* d_out, int out_size) {
    const float* f  = (const float*)d_in[0];
    const int*   lw = (const int*)d_in[1];
    float* out = (float*)d_out;

    cudaFuncSetAttribute(lse_mma_k, cudaFuncAttributeMaxDynamicSharedMemorySize, SMEM_BYTES);

    init_detect_k<<<1, 256>>>(lw);
    cvt_k<<<N_TOT, 128>>>(f, lw);
    vmask_k<<<N_TOT / 256, 256>>>();
    prep_k<<<256, 128>>>(f);
    lse_mma_k<<<NCTA, 256, SMEM_BYTES>>>();
    fin_k<<<FIN_BLOCKS, 256>>>(f);
    fin2_k<<<1, 128>>>(out);
}

// round 8
// speedup vs baseline: 3.1292x; 1.0981x over previous
#include <cuda_runtime.h>
#include <cuda_bf16.h>
#include <math.h>
#include <stdint.h>

// ---------------------------------------------------------------------------
// Problem constants
// ---------------------------------------------------------------------------
#define N_TOT 8192
#define D 128
#define TEMP_INV (1.0f/0.07f)
#define SCALE_LOG2 (1.44269504088896340736f/0.07f)   /* log2(e)/T */
#define LN2F 0.6931471805599453f
#define TILE 128
#define NCTA 152            /* GB300 has 152 SMs */
#define NUNITS 1024         /* 64 I-tiles x 16 J-chunks (4 tiles each) */
#define NSLOT 4             /* max partial-writers per I-block */
#define FIN_BLOCKS 128

// SMEM tile geometry: 128 rows x 128 bf16, padded row stride 136 elem (272 B)
#define PKB 272
#define TB  (128 * PKB)
#define OFF_A_HI 0
#define OFF_A_LO TB
#define OFF_B(b) (2*TB + (b)*(2*TB))   /* hi at +0, lo at +TB */
#define SMEM_BYTES (6*TB)              /* 208896 */

// ---------------------------------------------------------------------------
// Device scratch
// ---------------------------------------------------------------------------
__device__ __nv_bfloat16 g_hi[N_TOT * D];
__device__ __nv_bfloat16 g_lo[N_TOT * D];
__device__ float    g_G[2][D];
__device__ int      g_C[2];
__device__ int      g_cls[N_TOT];       /* 0 = invalid, 1 = class0, 2 = class1 */
__device__ float    g_pm[NSLOT][N_TOT]; /* log2-domain running max partials */
__device__ float    g_ps[NSLOT][N_TOT];
__device__ float    g_bsum[FIN_BLOCKS];
__device__ int      g_is64;

// ---------------------------------------------------------------------------
// Family-safe PTX helpers
// ---------------------------------------------------------------------------
__device__ __forceinline__ uint32_t smem_u32(const void* p) {
    uint32_t a;
    asm("{ .reg .u64 t; cvta.to.shared.u64 t, %1; cvt.u32.u64 %0, t; }" : "=r"(a) : "l"(p));
    return a;
}
__device__ __forceinline__ void ldsm4(uint32_t* r, uint32_t addr) {
    asm volatile("ldmatrix.sync.aligned.m8n8.x4.shared.b16 {%0,%1,%2,%3}, [%4];"
                 : "=r"(r[0]), "=r"(r[1]), "=r"(r[2]), "=r"(r[3]) : "r"(addr));
}
__device__ __forceinline__ void mma16816(float* c, const uint32_t* a, uint32_t b0, uint32_t b1) {
    asm volatile("mma.sync.aligned.m16n8k16.row.col.f32.bf16.bf16.f32 "
                 "{%0,%1,%2,%3}, {%4,%5,%6,%7}, {%8,%9}, {%0,%1,%2,%3};"
                 : "+f"(c[0]), "+f"(c[1]), "+f"(c[2]), "+f"(c[3])
                 : "r"(a[0]), "r"(a[1]), "r"(a[2]), "r"(a[3]), "r"(b0), "r"(b1));
}
__device__ __forceinline__ void cp16(uint32_t dst, const void* src) {
    asm volatile("cp.async.cg.shared.global [%0], [%1], 16;" :: "r"(dst), "l"(src));
}
#define CP_COMMIT() asm volatile("cp.async.commit_group;" ::: "memory")
#define CP_WAIT(n)  asm volatile("cp.async.wait_group %0;" :: "n"(n) : "memory")

__device__ __forceinline__ float ex2(float x) {
    float y;
    asm("ex2.approx.ftz.f32 %0, %1;" : "=f"(y) : "f"(x));
    return y;
}

// online-softmax merge, log2 domain
__device__ __forceinline__ void comb2(float& m, float& s, float m2, float s2) {
    float M = fmaxf(m, m2);
    float S;
    if (M == -INFINITY) S = 0.f;
    else S = ((m  == -INFINITY) ? 0.f : s  * ex2(m  - M))
           + ((m2 == -INFINITY) ? 0.f : s2 * ex2(m2 - M));
    m = M; s = S;
}

__device__ __forceinline__ void cp_tile(const __nv_bfloat16* __restrict__ src, int rowBase,
                                        uint32_t dstBase, int tid) {
    #pragma unroll
    for (int it = 0; it < 8; ++it) {
        int i = tid + it * 256;
        int row = i >> 4, c = i & 15;
        cp16(dstBase + row * PKB + c * 16, src + (size_t)(rowBase + row) * D + c * 8);
    }
}

// ---------------------------------------------------------------------------
// Kernel 0: zero class sums/counts + detect int64 vs int32 labels.
// ---------------------------------------------------------------------------
__global__ void init_detect_k(const int* __restrict__ lw) {
    int t = threadIdx.x;
    if (t < 2 * D) ((float*)g_G)[t] = 0.0f;
    if (t < 2)     g_C[t] = 0;
    int local = 0;
    for (int i = 1 + 2 * t; i < N_TOT; i += 2 * 256) local |= lw[i];
    __shared__ int anynz;
    if (t == 0) anynz = 0;
    __syncthreads();
    if (local) atomicOr(&anynz, 1);
    __syncthreads();
    if (t == 0) g_is64 = anynz ? 0 : 1;
}

// ---------------------------------------------------------------------------
// Kernel 1 (fused): bf16 hi/lo split + class code + partial-slot init.
// 512 blocks x 256 threads. One warp handles 2 rows (lane = one float4).
// ---------------------------------------------------------------------------
__global__ void cvt_k(const float* __restrict__ f, const int* __restrict__ lw) {
    const int tid = threadIdx.x, w = tid >> 5, lane = tid & 31;
    const int row0 = blockIdx.x * 16 + w * 2;
    const int is64 = g_is64;

    #pragma unroll
    for (int rr = 0; rr < 2; rr++) {
        int r = row0 + rr;
        float4 v = ((const float4*)(f + (size_t)r * D))[lane];
        __nv_bfloat16 hx = __float2bfloat16(v.x);
        __nv_bfloat16 hy = __float2bfloat16(v.y);
        __nv_bfloat16 hz = __float2bfloat16(v.z);
        __nv_bfloat16 hw = __float2bfloat16(v.w);
        __nv_bfloat162 hp0 = __halves2bfloat162(hx, hy);
        __nv_bfloat162 hp1 = __halves2bfloat162(hz, hw);
        __nv_bfloat162 lp0 = __halves2bfloat162(
            __float2bfloat16(v.x - __bfloat162float(hx)),
            __float2bfloat16(v.y - __bfloat162float(hy)));
        __nv_bfloat162 lp1 = __halves2bfloat162(
            __float2bfloat16(v.z - __bfloat162float(hz)),
            __float2bfloat16(v.w - __bfloat162float(hw)));
        uint2 H, L;
        H.x = *reinterpret_cast<uint32_t*>(&hp0);
        H.y = *reinterpret_cast<uint32_t*>(&hp1);
        L.x = *reinterpret_cast<uint32_t*>(&lp0);
        L.y = *reinterpret_cast<uint32_t*>(&lp1);
        *(uint2*)(g_hi + (size_t)r * D + lane * 4) = H;
        *(uint2*)(g_lo + (size_t)r * D + lane * 4) = L;

        uint32_t bal = __ballot_sync(0xffffffffu,
            (v.x != 0.f) || (v.y != 0.f) || (v.z != 0.f) || (v.w != 0.f));
        if (lane == 0) {
            int lab = is64 ? lw[2 * r] : lw[r];
            g_cls[r] = bal ? (lab + 1) : 0;
        }
    }

    // init partial slots: first 32768 global threads cover [NSLOT][N_TOT]
    int gt = blockIdx.x * 256 + tid;
    if (gt < NSLOT * N_TOT) {
        ((float*)g_pm)[gt] = -INFINITY;
        ((float*)g_ps)[gt] = 0.f;
    }
}

// ---------------------------------------------------------------------------
// Kernel 2: bf16-split GEMM (HMMA) + fused online logsumexp (log2 domain).
// 152 CTAs, statically balanced (<=2 segments each). Per-class feature sums
// (prep) fused into the prologue, overlapped with the first cp.async group.
// No validity masking needed: invalid rows are exactly zero -> dot = 0 ->
// ex2(0 - m) == 0 for valid anchors (m >= diag term ~2600 log2 units).
// ---------------------------------------------------------------------------
__global__ void __launch_bounds__(256, 1) lse_mma_k(const float* __restrict__ f) {
    extern __shared__ char smc[];
    const uint32_t base = smem_u32(smc);

    const int tid  = threadIdx.x;
    const int wid  = tid >> 5;
    const int lane = tid & 31;
    const int wrow = wid * 16;
    const int lrow = (lane & 7) + ((lane >> 3) & 1) * 8;
    const int lkof = (lane >> 4) * 16;

    // static unit range for this CTA
    const int c  = blockIdx.x;
    const int u0 = (c * NUNITS) / NCTA;
    const int u1 = ((c + 1) * NUNITS) / NCTA;

    int nseg, sI[2], sJA[2], sJB[2], sSl[2];
    {
        int I0 = u0 >> 4, bnd = (I0 + 1) << 4;
        int e1 = (u1 < bnd) ? u1 : bnd;
        sI[0] = I0;
        sJA[0] = (u0 & 15) * 4;
        sJB[0] = sJA[0] + (e1 - u0) * 4;
        sSl[0] = ((u0 & 15) + 5) / 6;
        if (u1 > bnd) { sI[1] = I0 + 1; sJA[1] = 0; sJB[1] = (u1 - bnd) * 4; sSl[1] = 0; nseg = 2; }
        else nseg = 1;
    }

    const uint32_t aHiB = base + OFF_A_HI + (wrow + lrow) * PKB + lkof;
    const uint32_t aLoB = base + OFF_A_LO + (wrow + lrow) * PKB + lkof;

    for (int g = 0; g < nseg; g++) {
        const int rowI = sI[g] * TILE;
        const int jA = sJA[g], jB = sJB[g];

        // segment prologue: A hi/lo + first B tile
        cp_tile(g_hi, rowI, base + OFF_A_HI, tid);
        cp_tile(g_lo, rowI, base + OFF_A_LO, tid);
        cp_tile(g_hi, jA * TILE, base + OFF_B(0), tid);
        cp_tile(g_lo, jA * TILE, base + OFF_B(0) + TB, tid);
        CP_COMMIT();

        // fused prep: per-class sums/counts for this CTA's row slice,
        // overlapped with the in-flight cp.async group. Once per CTA.
        if (g == 0) {
            const int rs = (c * N_TOT) / NCTA;
            const int re = ((c + 1) * N_TOT) / NCTA;   // re - rs <= 54
            const int k = tid & 127, h = tid >> 7;
            float a0 = 0.f, a1 = 0.f;
            for (int r = rs + h; r < re; r += 2) {
                int cls = g_cls[r];
                float v = f[(size_t)r * D + k];
                a0 += (cls == 1) ? v : 0.0f;
                a1 += (cls == 2) ? v : 0.0f;
            }
            atomicAdd(&g_G[0][k], a0);
            atomicAdd(&g_G[1][k], a1);
            if (tid < 64) {
                int cls = (rs + tid < re) ? g_cls[rs + tid] : 0;
                uint32_t b1 = __ballot_sync(0xffffffffu, cls == 1);
                uint32_t b2 = __ballot_sync(0xffffffffu, cls == 2);
                if ((tid & 31) == 0) {
                    atomicAdd(&g_C[0], __popc(b1));
                    atomicAdd(&g_C[1], __popc(b2));
                }
            }
        }

        float m0 = 0.f, s0 = 0.f;     // log2-domain; m=0 valid (no overflow,
        float m1 = 0.f, s1 = 0.f;     // diag term raises m for valid anchors)

        for (int jt = jA; jt < jB; jt++) {
            const int p = (jt - jA) & 1, q = p ^ 1;
            const int jb = jt * TILE;

            CP_WAIT(0);
            __syncthreads();

            if (jt + 1 < jB) {
                int jb2 = jb + TILE;
                cp_tile(g_hi, jb2, base + OFF_B(q), tid);
                cp_tile(g_lo, jb2, base + OFF_B(q) + TB, tid);
                CP_COMMIT();
            }

            float acc[16][4];
            #pragma unroll
            for (int nt = 0; nt < 16; nt++)
                #pragma unroll
                for (int cc = 0; cc < 4; cc++) acc[nt][cc] = 0.f;

            const uint32_t bHiB = base + OFF_B(p) + lrow * PKB + lkof;
            const uint32_t bLoB = bHiB + TB;

            #pragma unroll
            for (int ks = 0; ks < 8; ks++) {
                uint32_t aH[4], aL[4];
                ldsm4(aH, aHiB + ks * 32);
                ldsm4(aL, aLoB + ks * 32);
                #pragma unroll
                for (int nt2 = 0; nt2 < 8; nt2++) {
                    uint32_t bH[4], bL[4];
                    ldsm4(bH, bHiB + nt2 * (16 * PKB) + ks * 32);
                    ldsm4(bL, bLoB + nt2 * (16 * PKB) + ks * 32);
                    mma16816(acc[nt2 * 2 + 0], aH, bH[0], bH[2]);
                    mma16816(acc[nt2 * 2 + 1], aH, bH[1], bH[3]);
                    mma16816(acc[nt2 * 2 + 0], aL, bH[0], bH[2]);
                    mma16816(acc[nt2 * 2 + 1], aL, bH[1], bH[3]);
                    mma16816(acc[nt2 * 2 + 0], aH, bL[0], bL[2]);
                    mma16816(acc[nt2 * 2 + 1], aH, bL[1], bL[3]);
                }
            }

            // ---- epilogue: unmasked online max + sum-exp2 ----
            float tm0 = -INFINITY, tm1 = -INFINITY;
            #pragma unroll
            for (int nt = 0; nt < 16; nt++) {
                tm0 = fmaxf(tm0, fmaxf(acc[nt][0], acc[nt][1]));
                tm1 = fmaxf(tm1, fmaxf(acc[nt][2], acc[nt][3]));
            }
            float ts0 = tm0 * SCALE_LOG2, ts1 = tm1 * SCALE_LOG2;
            if (ts0 > m0) { s0 *= ex2(m0 - ts0); m0 = ts0; }
            if (ts1 > m1) { s1 *= ex2(m1 - ts1); m1 = ts1; }
            {
                float a0 = 0.f, a1 = 0.f, b0 = 0.f, b1 = 0.f;
                #pragma unroll
                for (int nt = 0; nt < 16; nt++) {
                    a0 += ex2(fmaf(acc[nt][0], SCALE_LOG2, -m0));
                    a1 += ex2(fmaf(acc[nt][1], SCALE_LOG2, -m0));
                    b0 += ex2(fmaf(acc[nt][2], SCALE_LOG2, -m1));
                    b1 += ex2(fmaf(acc[nt][3], SCALE_LOG2, -m1));
                }
                s0 += a0 + a1;
                s1 += b0 + b1;
            }
        }

        // quad combine + write this segment's partial into its slot
        #pragma unroll
        for (int off = 1; off <= 2; off <<= 1) {
            float mm = __shfl_xor_sync(0xffffffffu, m0, off);
            float ss = __shfl_xor_sync(0xffffffffu, s0, off);
            comb2(m0, s0, mm, ss);
            mm = __shfl_xor_sync(0xffffffffu, m1, off);
            ss = __shfl_xor_sync(0xffffffffu, s1, off);
            comb2(m1, s1, mm, ss);
        }
        if ((lane & 3) == 0) {
            int row = rowI + wrow + (lane >> 2);
            int sl = sSl[g];
            g_pm[sl][row]     = m0;
            g_ps[sl][row]     = s0;
            g_pm[sl][row + 8] = m1;
            g_ps[sl][row + 8] = s1;
        }
        __syncthreads();   // buffers free before next segment's prologue
    }
}

// ---------------------------------------------------------------------------
// Kernel 3: per-anchor finalize. 4 threads per anchor; combine NSLOT partials.
// ---------------------------------------------------------------------------
__global__ void fin_k(const float* __restrict__ f) {
    __shared__ float Gs[2 * D];
    __shared__ float red[64];
    const int t = threadIdx.x;
    if (t < 2 * D) Gs[t] = ((const float*)g_G)[t];
    __syncthreads();

    const int aIdx = t >> 2;
    const int qt   = t & 3;
    const int i    = blockIdx.x * 64 + aIdx;

    int cls = g_cls[i];
    float term = 0.f;

    float dot = 0.f;
    {
        int lab = (cls == 2) ? 1 : 0;
        const float4* fr = (const float4*)(f + (size_t)i * D) + qt * 8;
        const float4* gr = (const float4*)(Gs + lab * D) + qt * 8;
        #pragma unroll
        for (int k = 0; k < 8; k++) {
            float4 a = fr[k]; float4 g = gr[k];
            dot = fmaf(a.x, g.x, dot); dot = fmaf(a.y, g.y, dot);
            dot = fmaf(a.z, g.z, dot); dot = fmaf(a.w, g.w, dot);
        }
    }
    dot += __shfl_xor_sync(0xffffffffu, dot, 1);
    dot += __shfl_xor_sync(0xffffffffu, dot, 2);

    if (qt == 0 && cls != 0) {
        float M = g_pm[0][i], S = g_ps[0][i];
        comb2(M, S, g_pm[1][i], g_ps[1][i]);
        comb2(M, S, g_pm[2][i], g_ps[2][i]);
        comb2(M, S, g_pm[3][i], g_ps[3][i]);
        float lse = (M + log2f(S)) * LN2F;
        float cnt = (float)g_C[(cls == 2) ? 1 : 0];
        term = (cnt * lse - dot * TEMP_INV) * (1.0f / 128.0f);
    }

    if (qt == 0) red[aIdx] = term;
    __syncthreads();
    if (t < 32) {
        float v = red[t] + red[t + 32];
        #pragma unroll
        for (int off = 16; off > 0; off >>= 1)
            v += __shfl_xor_sync(0xffffffffu, v, off);
        if (t == 0) g_bsum[blockIdx.x] = v;
    }
}

__global__ void fin2_k(float* out) {
    int t = threadIdx.x;             // 128 threads
    float v = g_bsum[t];
    #pragma unroll
    for (int off = 16; off > 0; off >>= 1)
        v += __shfl_xor_sync(0xffffffffu, v, off);
    __shared__ float ws[4];
    if ((t & 31) == 0) ws[t >> 5] = v;
    __syncthreads();
    if (t == 0) out[0] = (ws[0] + ws[1] + ws[2] + ws[3]) * (1.0f / 256.0f);
}

// ---------------------------------------------------------------------------
extern "C" void kernel_launch(void* const* d_in, const int* in_sizes, int n_in,
                              void* d_out, int out_size) {
    const float* f  = (const float*)d_in[0];
    const int*   lw = (const int*)d_in[1];
    float* out = (float*)d_out;

    cudaFuncSetAttribute(lse_mma_k, cudaFuncAttributeMaxDynamicSharedMemorySize, SMEM_BYTES);

    init_detect_k<<<1, 256>>>(lw);
    cvt_k<<<N_TOT / 16, 256>>>(f, lw);
    lse_mma_k<<<NCTA, 256, SMEM_BYTES>>>(f);
    fin_k<<<FIN_BLOCKS, 256>>>(f);
    fin2_k<<<1, 128>>>(out);
}

// round 10
// speedup vs baseline: 3.3044x; 1.0560x over previous
#include <cuda_runtime.h>
#include <cuda_bf16.h>
#include <math.h>
#include <stdint.h>

// ---------------------------------------------------------------------------
// Problem constants
// ---------------------------------------------------------------------------
#define N_TOT 8192
#define D 128
#define TEMP_INV (1.0f/0.07f)
#define SCALE_LOG2 (1.44269504088896340736f/0.07f)   /* log2(e)/T */
#define LN2F 0.6931471805599453f
#define NCTA 304            /* 2 CTAs per SM x 152 SMs */
#define NUNITS 2048         /* 64 I-blocks x 32 units (unit = 256 J cols) */
#define NSLOT 8
#define FIN_BLOCKS 128

// SMEM: A = 128 rows x 128 bf16 (hi+lo resident), B = 32-row subtiles,
// double buffered. Padded row stride 272 B.
#define PKB 272
#define A_TB (128 * PKB)        /* 34816 */
#define B_TB (32 * PKB)         /* 8704  */
#define OFF_A_HI 0
#define OFF_A_LO A_TB
#define OFF_B(b) (2*A_TB + (b)*(2*B_TB))    /* hi at +0, lo at +B_TB */
#define SMEM_BYTES (2*A_TB + 4*B_TB)        /* 104448 -> 2 CTAs/SM */

// ---------------------------------------------------------------------------
// Device scratch
// ---------------------------------------------------------------------------
__device__ __nv_bfloat16 g_hi[N_TOT * D];
__device__ __nv_bfloat16 g_lo[N_TOT * D];
__device__ float    g_G[2][D];
__device__ int      g_C[2];
__device__ int      g_cls[N_TOT];       /* 0 invalid, 1 class0, 2 class1 */
__device__ float    g_pm[NSLOT][N_TOT]; /* log2-domain partial max */
__device__ float    g_ps[NSLOT][N_TOT];
__device__ float    g_bsum[FIN_BLOCKS];
__device__ int      g_is64;

// ---------------------------------------------------------------------------
// Family-safe PTX helpers
// ---------------------------------------------------------------------------
__device__ __forceinline__ uint32_t smem_u32(const void* p) {
    uint32_t a;
    asm("{ .reg .u64 t; cvta.to.shared.u64 t, %1; cvt.u32.u64 %0, t; }" : "=r"(a) : "l"(p));
    return a;
}
__device__ __forceinline__ void ldsm4(uint32_t* r, uint32_t addr) {
    asm volatile("ldmatrix.sync.aligned.m8n8.x4.shared.b16 {%0,%1,%2,%3}, [%4];"
                 : "=r"(r[0]), "=r"(r[1]), "=r"(r[2]), "=r"(r[3]) : "r"(addr));
}
__device__ __forceinline__ void mma16816(float* c, const uint32_t* a, uint32_t b0, uint32_t b1) {
    asm volatile("mma.sync.aligned.m16n8k16.row.col.f32.bf16.bf16.f32 "
                 "{%0,%1,%2,%3}, {%4,%5,%6,%7}, {%8,%9}, {%0,%1,%2,%3};"
                 : "+f"(c[0]), "+f"(c[1]), "+f"(c[2]), "+f"(c[3])
                 : "r"(a[0]), "r"(a[1]), "r"(a[2]), "r"(a[3]), "r"(b0), "r"(b1));
}
__device__ __forceinline__ void cp16(uint32_t dst, const void* src) {
    asm volatile("cp.async.cg.shared.global [%0], [%1], 16;" :: "r"(dst), "l"(src));
}
#define CP_COMMIT() asm volatile("cp.async.commit_group;" ::: "memory")
#define CP_WAIT(n)  asm volatile("cp.async.wait_group %0;" :: "n"(n) : "memory")

__device__ __forceinline__ float ex2(float x) {
    float y;
    asm("ex2.approx.ftz.f32 %0, %1;" : "=f"(y) : "f"(x));
    return y;
}

// online-softmax merge, log2 domain
__device__ __forceinline__ void comb2(float& m, float& s, float m2, float s2) {
    float M = fmaxf(m, m2);
    float S;
    if (M == -INFINITY) S = 0.f;
    else S = ((m  == -INFINITY) ? 0.f : s  * ex2(m  - M))
           + ((m2 == -INFINITY) ? 0.f : s2 * ex2(m2 - M));
    m = M; s = S;
}

// cp.async nrows x 128 bf16 rows into padded smem (16B chunks, 16 per row)
__device__ __forceinline__ void cp_rows(const __nv_bfloat16* __restrict__ src, int rowBase,
                                        uint32_t dstBase, int tid, int nthr, int nrows) {
    for (int i = tid; i < nrows * 16; i += nthr) {
        int row = i >> 4, c = i & 15;
        cp16(dstBase + row * PKB + c * 16, src + (size_t)(rowBase + row) * D + c * 8);
    }
}

// ---------------------------------------------------------------------------
// Kernel 0: zero class sums/counts + detect int64 vs int32 labels.
// ---------------------------------------------------------------------------
__global__ void init_detect_k(const int* __restrict__ lw) {
    int t = threadIdx.x;
    if (t < 2 * D) ((float*)g_G)[t] = 0.0f;
    if (t < 2)     g_C[t] = 0;
    int local = 0;
    for (int i = 1 + 2 * t; i < N_TOT; i += 2 * 256) local |= lw[i];
    __shared__ int anynz;
    if (t == 0) anynz = 0;
    __syncthreads();
    if (local) atomicOr(&anynz, 1);
    __syncthreads();
    if (t == 0) g_is64 = anynz ? 0 : 1;
}

// ---------------------------------------------------------------------------
// Kernel 1 (fused): bf16 hi/lo split + class code + partial-slot init.
// 512 blocks x 256 threads; one warp handles 2 rows.
// ---------------------------------------------------------------------------
__global__ void cvt_k(const float* __restrict__ f, const int* __restrict__ lw) {
    const int tid = threadIdx.x, w = tid >> 5, lane = tid & 31;
    const int row0 = blockIdx.x * 16 + w * 2;
    const int is64 = g_is64;

    #pragma unroll
    for (int rr = 0; rr < 2; rr++) {
        int r = row0 + rr;
        float4 v = ((const float4*)(f + (size_t)r * D))[lane];
        __nv_bfloat16 hx = __float2bfloat16(v.x);
        __nv_bfloat16 hy = __float2bfloat16(v.y);
        __nv_bfloat16 hz = __float2bfloat16(v.z);
        __nv_bfloat16 hw = __float2bfloat16(v.w);
        __nv_bfloat162 hp0 = __halves2bfloat162(hx, hy);
        __nv_bfloat162 hp1 = __halves2bfloat162(hz, hw);
        __nv_bfloat162 lp0 = __halves2bfloat162(
            __float2bfloat16(v.x - __bfloat162float(hx)),
            __float2bfloat16(v.y - __bfloat162float(hy)));
        __nv_bfloat162 lp1 = __halves2bfloat162(
            __float2bfloat16(v.z - __bfloat162float(hz)),
            __float2bfloat16(v.w - __bfloat162float(hw)));
        uint2 H, L;
        H.x = *reinterpret_cast<uint32_t*>(&hp0);
        H.y = *reinterpret_cast<uint32_t*>(&hp1);
        L.x = *reinterpret_cast<uint32_t*>(&lp0);
        L.y = *reinterpret_cast<uint32_t*>(&lp1);
        *(uint2*)(g_hi + (size_t)r * D + lane * 4) = H;
        *(uint2*)(g_lo + (size_t)r * D + lane * 4) = L;

        uint32_t bal = __ballot_sync(0xffffffffu,
            (v.x != 0.f) || (v.y != 0.f) || (v.z != 0.f) || (v.w != 0.f));
        if (lane == 0) {
            int lab = is64 ? lw[2 * r] : lw[r];
            g_cls[r] = bal ? (lab + 1) : 0;
        }
    }

    // init partial slots: NSLOT*N_TOT = 65536 elements
    int gt = blockIdx.x * 256 + tid;
    if (gt < NSLOT * N_TOT) {
        ((float*)g_pm)[gt] = -INFINITY;
        ((float*)g_ps)[gt] = 0.f;
    }
}

// ---------------------------------------------------------------------------
// Kernel 2: bf16-split GEMM (HMMA) + fused online logsumexp (log2 domain).
// 304 CTAs x 128 threads -> 2 CTAs/SM: independent CTA phases keep the
// tensor pipe busy while the peer CTA runs its MUFU epilogue.
// Per CTA: A-block (128 rows) resident, B 32-col subtiles double-buffered.
// Warp owns 32 rows x 32 cols (acc[2][4][4]).
// ---------------------------------------------------------------------------
__global__ void __launch_bounds__(128, 2) lse_mma_k(const float* __restrict__ f) {
    extern __shared__ char smc[];
    const uint32_t base = smem_u32(smc);

    const int tid  = threadIdx.x;
    const int wid  = tid >> 5;
    const int lane = tid & 31;
    const int wrow = wid * 32;
    const int lrow = (lane & 7) + ((lane >> 3) & 1) * 8;
    const int lkof = (lane >> 4) * 16;

    // static unit range (unit = one I-block x 256 J cols = 8 subtiles)
    const int c  = blockIdx.x;
    const int u0 = (c * NUNITS) / NCTA;
    const int u1 = ((c + 1) * NUNITS) / NCTA;

    int nseg, sI[2], sA[2], sB[2], sSl[2];
    {
        int I0 = u0 >> 5, bnd = (I0 + 1) << 5;
        int e1 = (u1 < bnd) ? u1 : bnd;
        sI[0] = I0;
        sA[0] = (u0 & 31) * 8;
        sB[0] = sA[0] + (e1 - u0) * 8;
        sSl[0] = c - (19 * I0) / 4;             // c - first CTA covering block
        if (u1 > bnd) {
            sI[1] = I0 + 1; sA[1] = 0; sB[1] = (u1 - bnd) * 8;
            sSl[1] = c - (19 * (I0 + 1)) / 4;
            nseg = 2;
        } else nseg = 1;
    }

    const uint32_t aH0 = base + OFF_A_HI + (wrow + lrow) * PKB + lkof;
    const uint32_t aL0 = base + OFF_A_LO + (wrow + lrow) * PKB + lkof;

    for (int g = 0; g < nseg; g++) {
        const int rowI = sI[g] * 128;
        const int jA = sA[g], jB = sB[g];          // subtile indices (32 cols)

        // segment prologue: A hi/lo (128 rows) + first B subtile
        cp_rows(g_hi, rowI, base + OFF_A_HI, tid, 128, 128);
        cp_rows(g_lo, rowI, base + OFF_A_LO, tid, 128, 128);
        cp_rows(g_hi, jA * 32, base + OFF_B(0), tid, 128, 32);
        cp_rows(g_lo, jA * 32, base + OFF_B(0) + B_TB, tid, 128, 32);
        CP_COMMIT();

        // fused prep (once per CTA), overlapped with in-flight cp.async
        if (g == 0) {
            const int rs = (c * N_TOT) / NCTA;
            const int re = ((c + 1) * N_TOT) / NCTA;   // <= 27 rows
            float a0 = 0.f, a1 = 0.f;
            for (int r = rs; r < re; r++) {
                int cls = g_cls[r];
                float v = f[(size_t)r * D + tid];
                a0 += (cls == 1) ? v : 0.0f;
                a1 += (cls == 2) ? v : 0.0f;
            }
            atomicAdd(&g_G[0][tid], a0);
            atomicAdd(&g_G[1][tid], a1);
            if (tid < 32) {
                int cls = (rs + tid < re) ? g_cls[rs + tid] : 0;
                uint32_t b1 = __ballot_sync(0xffffffffu, cls == 1);
                uint32_t b2 = __ballot_sync(0xffffffffu, cls == 2);
                if (tid == 0) {
                    atomicAdd(&g_C[0], __popc(b1));
                    atomicAdd(&g_C[1], __popc(b2));
                }
            }
        }

        // running (m,s): 4 pairs -> rows wrow + mb*16 + h*8 + (lane>>2)
        float mrun[4], srun[4];
        #pragma unroll
        for (int i = 0; i < 4; i++) { mrun[i] = 0.f; srun[i] = 0.f; }

        for (int s = jA; s < jB; s++) {
            const int p = (s - jA) & 1, q = p ^ 1;

            CP_WAIT(0);
            __syncthreads();

            if (s + 1 < jB) {
                cp_rows(g_hi, (s + 1) * 32, base + OFF_B(q), tid, 128, 32);
                cp_rows(g_lo, (s + 1) * 32, base + OFF_B(q) + B_TB, tid, 128, 32);
                CP_COMMIT();
            }

            float acc[2][4][4];
            #pragma unroll
            for (int mb = 0; mb < 2; mb++)
                #pragma unroll
                for (int nt = 0; nt < 4; nt++)
                    #pragma unroll
                    for (int cc = 0; cc < 4; cc++) acc[mb][nt][cc] = 0.f;

            const uint32_t bHiB = base + OFF_B(p) + lrow * PKB + lkof;
            const uint32_t bLoB = bHiB + B_TB;

            #pragma unroll
            for (int ks = 0; ks < 8; ks++) {
                uint32_t aH[2][4], aL[2][4];
                ldsm4(aH[0], aH0 + ks * 32);
                ldsm4(aH[1], aH0 + 16 * PKB + ks * 32);
                ldsm4(aL[0], aL0 + ks * 32);
                ldsm4(aL[1], aL0 + 16 * PKB + ks * 32);
                #pragma unroll
                for (int np = 0; np < 2; np++) {
                    uint32_t bH[4], bL[4];
                    ldsm4(bH, bHiB + np * (16 * PKB) + ks * 32);
                    ldsm4(bL, bLoB + np * (16 * PKB) + ks * 32);
                    #pragma unroll
                    for (int mb = 0; mb < 2; mb++) {
                        mma16816(acc[mb][np * 2 + 0], aH[mb], bH[0], bH[2]);
                        mma16816(acc[mb][np * 2 + 1], aH[mb], bH[1], bH[3]);
                        mma16816(acc[mb][np * 2 + 0], aL[mb], bH[0], bH[2]);
                        mma16816(acc[mb][np * 2 + 1], aL[mb], bH[1], bH[3]);
                        mma16816(acc[mb][np * 2 + 0], aH[mb], bL[0], bL[2]);
                        mma16816(acc[mb][np * 2 + 1], aH[mb], bL[1], bL[3]);
                    }
                }
            }

            // epilogue: unmasked online max + sum-exp2 (4 running pairs)
            #pragma unroll
            for (int mb = 0; mb < 2; mb++) {
                float tm0 = -INFINITY, tm1 = -INFINITY;
                #pragma unroll
                for (int nt = 0; nt < 4; nt++) {
                    tm0 = fmaxf(tm0, fmaxf(acc[mb][nt][0], acc[mb][nt][1]));
                    tm1 = fmaxf(tm1, fmaxf(acc[mb][nt][2], acc[mb][nt][3]));
                }
                float ts0 = tm0 * SCALE_LOG2, ts1 = tm1 * SCALE_LOG2;
                int i0 = mb * 2, i1 = mb * 2 + 1;
                if (ts0 > mrun[i0]) { srun[i0] *= ex2(mrun[i0] - ts0); mrun[i0] = ts0; }
                if (ts1 > mrun[i1]) { srun[i1] *= ex2(mrun[i1] - ts1); mrun[i1] = ts1; }
                float a0 = 0.f, a1 = 0.f, b0 = 0.f, b1 = 0.f;
                #pragma unroll
                for (int nt = 0; nt < 4; nt++) {
                    a0 += ex2(fmaf(acc[mb][nt][0], SCALE_LOG2, -mrun[i0]));
                    a1 += ex2(fmaf(acc[mb][nt][1], SCALE_LOG2, -mrun[i0]));
                    b0 += ex2(fmaf(acc[mb][nt][2], SCALE_LOG2, -mrun[i1]));
                    b1 += ex2(fmaf(acc[mb][nt][3], SCALE_LOG2, -mrun[i1]));
                }
                srun[i0] += a0 + a1;
                srun[i1] += b0 + b1;
            }
        }

        // quad combine + write 4 partial rows into this segment's slot
        #pragma unroll
        for (int i = 0; i < 4; i++) {
            #pragma unroll
            for (int off = 1; off <= 2; off <<= 1) {
                float mm = __shfl_xor_sync(0xffffffffu, mrun[i], off);
                float ss = __shfl_xor_sync(0xffffffffu, srun[i], off);
                comb2(mrun[i], srun[i], mm, ss);
            }
        }
        if ((lane & 3) == 0) {
            int sl = sSl[g];
            int r0 = rowI + wrow + (lane >> 2);
            g_pm[sl][r0]      = mrun[0];
            g_ps[sl][r0]      = srun[0];
            g_pm[sl][r0 + 8]  = mrun[1];
            g_ps[sl][r0 + 8]  = srun[1];
            g_pm[sl][r0 + 16] = mrun[2];
            g_ps[sl][r0 + 16] = srun[2];
            g_pm[sl][r0 + 24] = mrun[3];
            g_ps[sl][r0 + 24] = srun[3];
        }
        __syncthreads();   // buffers free before next segment's prologue
    }
}

// ---------------------------------------------------------------------------
// Kernel 3: per-anchor finalize. 4 threads/anchor: each combines 2 slots,
// quad-butterfly merges (m,s) and the dot product.
// ---------------------------------------------------------------------------
__global__ void fin_k(const float* __restrict__ f) {
    __shared__ float Gs[2 * D];
    __shared__ float red[64];
    const int t = threadIdx.x;
    Gs[t] = ((const float*)g_G)[t];
    __syncthreads();

    const int aIdx = t >> 2;
    const int qt   = t & 3;
    const int i    = blockIdx.x * 64 + aIdx;

    int cls = g_cls[i];

    // each quad thread combines slots qt and qt+4
    float M = g_pm[qt][i], S = g_ps[qt][i];
    comb2(M, S, g_pm[qt + 4][i], g_ps[qt + 4][i]);

    // quad-split dot
    float dot = 0.f;
    {
        int lab = (cls == 2) ? 1 : 0;
        const float4* fr = (const float4*)(f + (size_t)i * D) + qt * 8;
        const float4* gr = (const float4*)(Gs + lab * D) + qt * 8;
        #pragma unroll
        for (int k = 0; k < 8; k++) {
            float4 a = fr[k]; float4 g = gr[k];
            dot = fmaf(a.x, g.x, dot); dot = fmaf(a.y, g.y, dot);
            dot = fmaf(a.z, g.z, dot); dot = fmaf(a.w, g.w, dot);
        }
    }

    // quad butterfly: merge (M,S) and dot
    #pragma unroll
    for (int off = 1; off <= 2; off <<= 1) {
        float mm = __shfl_xor_sync(0xffffffffu, M, off);
        float ss = __shfl_xor_sync(0xffffffffu, S, off);
        comb2(M, S, mm, ss);
        dot += __shfl_xor_sync(0xffffffffu, dot, off);
    }

    float term = 0.f;
    if (qt == 0 && cls != 0) {
        float lse = (M + log2f(S)) * LN2F;
        float cnt = (float)g_C[(cls == 2) ? 1 : 0];
        term = (cnt * lse - dot * TEMP_INV) * (1.0f / 128.0f);
    }

    if (qt == 0) red[aIdx] = term;
    __syncthreads();
    if (t < 32) {
        float v = red[t] + red[t + 32];
        #pragma unroll
        for (int off = 16; off > 0; off >>= 1)
            v += __shfl_xor_sync(0xffffffffu, v, off);
        if (t == 0) g_bsum[blockIdx.x] = v;
    }
}

__global__ void fin2_k(float* out) {
    int t = threadIdx.x;             // 128 threads
    float v = g_bsum[t];
    #pragma unroll
    for (int off = 16; off > 0; off >>= 1)
        v += __shfl_xor_sync(0xffffffffu, v, off);
    __shared__ float ws[4];
    if ((t & 31) == 0) ws[t >> 5] = v;
    __syncthreads();
    if (t == 0) out[0] = (ws[0] + ws[1] + ws[2] + ws[3]) * (1.0f / 256.0f);
}

// ---------------------------------------------------------------------------
extern "C" void kernel_launch(void* const* d_in, const int* in_sizes, int n_in,
                              void* d_out, int out_size) {
    const float* f  = (const float*)d_in[0];
    const int*   lw = (const int*)d_in[1];
    float* out = (float*)d_out;

    cudaFuncSetAttribute(lse_mma_k, cudaFuncAttributeMaxDynamicSharedMemorySize, SMEM_BYTES);

    init_detect_k<<<1, 256>>>(lw);
    cvt_k<<<N_TOT / 16, 256>>>(f, lw);
    lse_mma_k<<<NCTA, 128, SMEM_BYTES>>>(f);
    fin_k<<<FIN_BLOCKS, 256>>>(f);
    fin2_k<<<1, 128>>>(out);
}

// round 12
// speedup vs baseline: 5.8371x; 1.7665x over previous
#include <cuda_runtime.h>
#include <cuda_bf16.h>
#include <math.h>
#include <stdint.h>

// ---------------------------------------------------------------------------
// Problem constants
// ---------------------------------------------------------------------------
#define N_TOT 8192
#define D 128
#define TEMP_INV (1.0f/0.07f)
#define SCALE_LOG2 (1.44269504088896340736f/0.07f)   /* log2(e)/T */
#define LN2F 0.6931471805599453f
#define NCTA 608            /* 4 CTAs per SM x 152 SMs */
#define NUNITS 2048         /* 64 I-blocks x 32 units (unit = 256 J cols) */
#define NSLOT 16            /* slot = cta & 15; span per I-block <= 12 */
#define FIN_BLOCKS 128

// SMEM: A = 128 rows x 128 bf16 (hi only, resident), B = 32-row subtiles,
// double buffered. Padded row stride 272 B.
#define PKB 272
#define A_TB (128 * PKB)        /* 34816 */
#define B_TB (32 * PKB)         /* 8704  */
#define OFF_A 0
#define OFF_B(b) (A_TB + (b)*B_TB)
#define SMEM_BYTES (A_TB + 2*B_TB)   /* 52224 -> 4 CTAs/SM */

// ---------------------------------------------------------------------------
// Device scratch
// ---------------------------------------------------------------------------
__device__ __nv_bfloat16 g_hi[N_TOT * D];
__device__ float    g_norm[N_TOT];      /* |f_i|^2, fp32 exact */
__device__ float    g_G[2][D];
__device__ int      g_C[2];
__device__ int      g_cls[N_TOT];       /* 0 invalid, 1 class0, 2 class1 */
__device__ float    g_pm[NSLOT][N_TOT]; /* log2-domain partial max */
__device__ float    g_ps[NSLOT][N_TOT];
__device__ float    g_bsum[FIN_BLOCKS];
__device__ int      g_is64;

// ---------------------------------------------------------------------------
// Family-safe PTX helpers
// ---------------------------------------------------------------------------
__device__ __forceinline__ uint32_t smem_u32(const void* p) {
    uint32_t a;
    asm("{ .reg .u64 t; cvta.to.shared.u64 t, %1; cvt.u32.u64 %0, t; }" : "=r"(a) : "l"(p));
    return a;
}
__device__ __forceinline__ void ldsm4(uint32_t* r, uint32_t addr) {
    asm volatile("ldmatrix.sync.aligned.m8n8.x4.shared.b16 {%0,%1,%2,%3}, [%4];"
                 : "=r"(r[0]), "=r"(r[1]), "=r"(r[2]), "=r"(r[3]) : "r"(addr));
}
__device__ __forceinline__ void mma16816(float* c, const uint32_t* a, uint32_t b0, uint32_t b1) {
    asm volatile("mma.sync.aligned.m16n8k16.row.col.f32.bf16.bf16.f32 "
                 "{%0,%1,%2,%3}, {%4,%5,%6,%7}, {%8,%9}, {%0,%1,%2,%3};"
                 : "+f"(c[0]), "+f"(c[1]), "+f"(c[2]), "+f"(c[3])
                 : "r"(a[0]), "r"(a[1]), "r"(a[2]), "r"(a[3]), "r"(b0), "r"(b1));
}
__device__ __forceinline__ void cp16(uint32_t dst, const void* src) {
    asm volatile("cp.async.cg.shared.global [%0], [%1], 16;" :: "r"(dst), "l"(src));
}
#define CP_COMMIT() asm volatile("cp.async.commit_group;" ::: "memory")
#define CP_WAIT(n)  asm volatile("cp.async.wait_group %0;" :: "n"(n) : "memory")

__device__ __forceinline__ float ex2(float x) {
    float y;
    asm("ex2.approx.ftz.f32 %0, %1;" : "=f"(y) : "f"(x));
    return y;
}

// online-softmax merge, log2 domain
__device__ __forceinline__ void comb2(float& m, float& s, float m2, float s2) {
    float M = fmaxf(m, m2);
    float S;
    if (M == -INFINITY) S = 0.f;
    else S = ((m  == -INFINITY) ? 0.f : s  * ex2(m  - M))
           + ((m2 == -INFINITY) ? 0.f : s2 * ex2(m2 - M));
    m = M; s = S;
}

// cp.async nrows x 128 bf16 rows into padded smem (16B chunks, 16 per row)
__device__ __forceinline__ void cp_rows(const __nv_bfloat16* __restrict__ src, int rowBase,
                                        uint32_t dstBase, int tid, int nthr, int nrows) {
    for (int i = tid; i < nrows * 16; i += nthr) {
        int row = i >> 4, c = i & 15;
        cp16(dstBase + row * PKB + c * 16, src + (size_t)(rowBase + row) * D + c * 8);
    }
}

// ---------------------------------------------------------------------------
// Kernel 0: zero class sums/counts + detect int64 vs int32 labels.
// ---------------------------------------------------------------------------
__global__ void init_detect_k(const int* __restrict__ lw) {
    int t = threadIdx.x;
    if (t < 2 * D) ((float*)g_G)[t] = 0.0f;
    if (t < 2)     g_C[t] = 0;
    int local = 0;
    for (int i = 1 + 2 * t; i < N_TOT; i += 2 * 256) local |= lw[i];
    __shared__ int anynz;
    if (t == 0) anynz = 0;
    __syncthreads();
    if (local) atomicOr(&anynz, 1);
    __syncthreads();
    if (t == 0) g_is64 = anynz ? 0 : 1;
}

// ---------------------------------------------------------------------------
// Kernel 1 (fused): bf16 hi split + exact fp32 norms + class code +
// per-class sums/counts (shared staging) + partial-slot init.
// 512 blocks x 256 threads; one warp handles 2 rows.
// ---------------------------------------------------------------------------
__global__ void cvt_k(const float* __restrict__ f, const int* __restrict__ lw) {
    __shared__ float sG[2 * D];
    __shared__ int   sC[2];
    const int tid = threadIdx.x, w = tid >> 5, lane = tid & 31;
    const int row0 = blockIdx.x * 16 + w * 2;
    const int is64 = g_is64;

    sG[tid] = 0.f;
    if (tid < 2) sC[tid] = 0;
    __syncthreads();

    #pragma unroll
    for (int rr = 0; rr < 2; rr++) {
        int r = row0 + rr;
        float4 v = ((const float4*)(f + (size_t)r * D))[lane];
        __nv_bfloat16 hx = __float2bfloat16(v.x);
        __nv_bfloat16 hy = __float2bfloat16(v.y);
        __nv_bfloat16 hz = __float2bfloat16(v.z);
        __nv_bfloat16 hw = __float2bfloat16(v.w);
        __nv_bfloat162 hp0 = __halves2bfloat162(hx, hy);
        __nv_bfloat162 hp1 = __halves2bfloat162(hz, hw);
        uint2 H;
        H.x = *reinterpret_cast<uint32_t*>(&hp0);
        H.y = *reinterpret_cast<uint32_t*>(&hp1);
        *(uint2*)(g_hi + (size_t)r * D + lane * 4) = H;

        // exact fp32 norm (warp reduce)
        float sq = v.x * v.x + v.y * v.y + v.z * v.z + v.w * v.w;
        #pragma unroll
        for (int off = 16; off > 0; off >>= 1)
            sq += __shfl_xor_sync(0xffffffffu, sq, off);

        uint32_t bal = __ballot_sync(0xffffffffu,
            (v.x != 0.f) || (v.y != 0.f) || (v.z != 0.f) || (v.w != 0.f));
        int lab = is64 ? lw[2 * r] : lw[r];
        int cls = bal ? (lab + 1) : 0;
        if (lane == 0) {
            g_cls[r]  = cls;
            g_norm[r] = sq;
        }
        if (cls) {
            float* dst = sG + (cls - 1) * D + lane * 4;
            atomicAdd(dst + 0, v.x);
            atomicAdd(dst + 1, v.y);
            atomicAdd(dst + 2, v.z);
            atomicAdd(dst + 3, v.w);
            if (lane == 0) atomicAdd(&sC[cls - 1], 1);
        }
    }
    __syncthreads();
    atomicAdd(&((float*)g_G)[tid], sG[tid]);
    if (tid < 2) atomicAdd(&g_C[tid], sC[tid]);

    // init partial slots: NSLOT*N_TOT = 131072 = grid size exactly
    int gt = blockIdx.x * 256 + tid;
    ((float*)g_pm)[gt] = -INFINITY;
    ((float*)g_ps)[gt] = 0.f;
}

// ---------------------------------------------------------------------------
// Kernel 2: pure-bf16 GEMM (HMMA) + fused online logsumexp (log2 domain).
// 608 CTAs x 128 threads (4/SM). Off-diagonal needs only bf16 accuracy
// (terms are e^-1500 relative to the diagonal); the diagonal element is
// EXCLUDED here (masked -inf) and merged exactly from fp32 norms in fin_k.
// ex2 bursts skipped when a subtile group is >=64 log2 below running max.
// ---------------------------------------------------------------------------
__global__ void __launch_bounds__(128, 4) lse_mma_k() {
    extern __shared__ char smc[];
    const uint32_t base = smem_u32(smc);

    const int tid  = threadIdx.x;
    const int wid  = tid >> 5;
    const int lane = tid & 31;
    const int wrow = wid * 32;
    const int lrow = (lane & 7) + ((lane >> 3) & 1) * 8;
    const int lkof = (lane >> 4) * 16;

    const int c  = blockIdx.x;
    const int u0 = (c * NUNITS) / NCTA;
    const int u1 = ((c + 1) * NUNITS) / NCTA;

    int nseg, sI[2], sA[2], sB[2];
    {
        int I0 = u0 >> 5, bnd = (I0 + 1) << 5;
        int e1 = (u1 < bnd) ? u1 : bnd;
        sI[0] = I0;
        sA[0] = (u0 & 31) * 8;                 // subtile indices (32 cols each)
        sB[0] = sA[0] + (e1 - u0) * 8;
        if (u1 > bnd) { sI[1] = I0 + 1; sA[1] = 0; sB[1] = (u1 - bnd) * 8; nseg = 2; }
        else nseg = 1;
    }
    const int slot = c & (NSLOT - 1);

    const uint32_t aB = base + OFF_A + (wrow + lrow) * PKB + lkof;

    for (int g = 0; g < nseg; g++) {
        const int rowI = sI[g] * 128;
        const int jA = sA[g], jB = sB[g];

        cp_rows(g_hi, rowI, base + OFF_A, tid, 128, 128);
        cp_rows(g_hi, jA * 32, base + OFF_B(0), tid, 128, 32);
        CP_COMMIT();

        float mrun[4], srun[4];
        #pragma unroll
        for (int i = 0; i < 4; i++) { mrun[i] = 0.f; srun[i] = 0.f; }

        for (int s = jA; s < jB; s++) {
            const int p = (s - jA) & 1, q = p ^ 1;

            CP_WAIT(0);
            __syncthreads();

            if (s + 1 < jB) {
                cp_rows(g_hi, (s + 1) * 32, base + OFF_B(q), tid, 128, 32);
                CP_COMMIT();
            }

            float acc[2][4][4];
            #pragma unroll
            for (int mb = 0; mb < 2; mb++)
                #pragma unroll
                for (int nt = 0; nt < 4; nt++)
                    #pragma unroll
                    for (int cc = 0; cc < 4; cc++) acc[mb][nt][cc] = 0.f;

            const uint32_t bB = base + OFF_B(p) + lrow * PKB + lkof;

            #pragma unroll
            for (int ks = 0; ks < 8; ks++) {
                uint32_t aH[2][4];
                ldsm4(aH[0], aB + ks * 32);
                ldsm4(aH[1], aB + 16 * PKB + ks * 32);
                #pragma unroll
                for (int np = 0; np < 2; np++) {
                    uint32_t bH[4];
                    ldsm4(bH, bB + np * (16 * PKB) + ks * 32);
                    #pragma unroll
                    for (int mb = 0; mb < 2; mb++) {
                        mma16816(acc[mb][np * 2 + 0], aH[mb], bH[0], bH[2]);
                        mma16816(acc[mb][np * 2 + 1], aH[mb], bH[1], bH[3]);
                    }
                }
            }

            // exclude exact-diagonal elements (merged exactly in fin_k)
            if (s * 32 == rowI + wrow) {
                #pragma unroll
                for (int mb = 0; mb < 2; mb++)
                    #pragma unroll
                    for (int nt = 0; nt < 4; nt++)
                        #pragma unroll
                        for (int cc = 0; cc < 4; cc++) {
                            int rl = mb * 16 + ((cc >> 1) << 3) + (lane >> 2);
                            int cl = nt * 8 + ((lane & 3) << 1) + (cc & 1);
                            if (rl == cl) acc[mb][nt][cc] = -INFINITY;
                        }
            }

            // epilogue: online max + (skippable) sum-exp2
            #pragma unroll
            for (int mb = 0; mb < 2; mb++) {
                float tm0 = -INFINITY, tm1 = -INFINITY;
                #pragma unroll
                for (int nt = 0; nt < 4; nt++) {
                    tm0 = fmaxf(tm0, fmaxf(acc[mb][nt][0], acc[mb][nt][1]));
                    tm1 = fmaxf(tm1, fmaxf(acc[mb][nt][2], acc[mb][nt][3]));
                }
                float ts0 = tm0 * SCALE_LOG2, ts1 = tm1 * SCALE_LOG2;
                int i0 = mb * 2, i1 = i0 + 1;
                if (ts0 > mrun[i0]) { srun[i0] *= ex2(mrun[i0] - ts0); mrun[i0] = ts0; }
                if (ts0 >= mrun[i0] - 64.0f) {       // dropped terms < 2^-64
                    float a0 = 0.f, a1 = 0.f;
                    #pragma unroll
                    for (int nt = 0; nt < 4; nt++) {
                        a0 += ex2(fmaf(acc[mb][nt][0], SCALE_LOG2, -mrun[i0]));
                        a1 += ex2(fmaf(acc[mb][nt][1], SCALE_LOG2, -mrun[i0]));
                    }
                    srun[i0] += a0 + a1;
                }
                if (ts1 > mrun[i1]) { srun[i1] *= ex2(mrun[i1] - ts1); mrun[i1] = ts1; }
                if (ts1 >= mrun[i1] - 64.0f) {
                    float b0 = 0.f, b1 = 0.f;
                    #pragma unroll
                    for (int nt = 0; nt < 4; nt++) {
                        b0 += ex2(fmaf(acc[mb][nt][2], SCALE_LOG2, -mrun[i1]));
                        b1 += ex2(fmaf(acc[mb][nt][3], SCALE_LOG2, -mrun[i1]));
                    }
                    srun[i1] += b0 + b1;
                }
            }
        }

        // quad combine + write partial rows into this CTA's slot
        #pragma unroll
        for (int i = 0; i < 4; i++) {
            #pragma unroll
            for (int off = 1; off <= 2; off <<= 1) {
                float mm = __shfl_xor_sync(0xffffffffu, mrun[i], off);
                float ss = __shfl_xor_sync(0xffffffffu, srun[i], off);
                comb2(mrun[i], srun[i], mm, ss);
            }
        }
        if ((lane & 3) == 0) {
            int r0 = rowI + wrow + (lane >> 2);
            g_pm[slot][r0]      = mrun[0];
            g_ps[slot][r0]      = srun[0];
            g_pm[slot][r0 + 8]  = mrun[1];
            g_ps[slot][r0 + 8]  = srun[1];
            g_pm[slot][r0 + 16] = mrun[2];
            g_ps[slot][r0 + 16] = srun[2];
            g_pm[slot][r0 + 24] = mrun[3];
            g_ps[slot][r0 + 24] = srun[3];
        }
        __syncthreads();   // buffers free before next segment's prologue
    }
}

// ---------------------------------------------------------------------------
// Kernel 3: per-anchor finalize. 4 threads/anchor: each combines 4 slots,
// quad-butterfly merges (m,s) + dot; exact diagonal merged from fp32 norm.
// ---------------------------------------------------------------------------
__global__ void fin_k(const float* __restrict__ f) {
    __shared__ float Gs[2 * D];
    __shared__ float red[64];
    const int t = threadIdx.x;
    Gs[t] = ((const float*)g_G)[t];
    __syncthreads();

    const int aIdx = t >> 2;
    const int qt   = t & 3;
    const int i    = blockIdx.x * 64 + aIdx;

    int cls = g_cls[i];

    float M = -INFINITY, S = 0.f;
    #pragma unroll
    for (int s = 0; s < 4; s++)
        comb2(M, S, g_pm[qt + s * 4][i], g_ps[qt + s * 4][i]);

    // quad-split dot with G
    float dot = 0.f;
    {
        int lab = (cls == 2) ? 1 : 0;
        const float4* fr = (const float4*)(f + (size_t)i * D) + qt * 8;
        const float4* gr = (const float4*)(Gs + lab * D) + qt * 8;
        #pragma unroll
        for (int k = 0; k < 8; k++) {
            float4 a = fr[k]; float4 g = gr[k];
            dot = fmaf(a.x, g.x, dot); dot = fmaf(a.y, g.y, dot);
            dot = fmaf(a.z, g.z, dot); dot = fmaf(a.w, g.w, dot);
        }
    }

    #pragma unroll
    for (int off = 1; off <= 2; off <<= 1) {
        float mm = __shfl_xor_sync(0xffffffffu, M, off);
        float ss = __shfl_xor_sync(0xffffffffu, S, off);
        comb2(M, S, mm, ss);
        dot += __shfl_xor_sync(0xffffffffu, dot, off);
    }

    float term = 0.f;
    if (qt == 0 && cls != 0) {
        comb2(M, S, g_norm[i] * SCALE_LOG2, 1.0f);   // exact diagonal
        float lse = (M + log2f(S)) * LN2F;
        float cnt = (float)g_C[(cls == 2) ? 1 : 0];
        term = (cnt * lse - dot * TEMP_INV) * (1.0f / 128.0f);
    }

    if (qt == 0) red[aIdx] = term;
    __syncthreads();
    if (t < 32) {
        float v = red[t] + red[t + 32];
        #pragma unroll
        for (int off = 16; off > 0; off >>= 1)
            v += __shfl_xor_sync(0xffffffffu, v, off);
        if (t == 0) g_bsum[blockIdx.x] = v;
    }
}

__global__ void fin2_k(float* out) {
    int t = threadIdx.x;             // 128 threads
    float v = g_bsum[t];
    #pragma unroll
    for (int off = 16; off > 0; off >>= 1)
        v += __shfl_xor_sync(0xffffffffu, v, off);
    __shared__ float ws[4];
    if ((t & 31) == 0) ws[t >> 5] = v;
    __syncthreads();
    if (t == 0) out[0] = (ws[0] + ws[1] + ws[2] + ws[3]) * (1.0f / 256.0f);
}

// ---------------------------------------------------------------------------
extern "C" void kernel_launch(void* const* d_in, const int* in_sizes, int n_in,
                              void* d_out, int out_size) {
    const float* f  = (const float*)d_in[0];
    const int*   lw = (const int*)d_in[1];
    float* out = (float*)d_out;

    cudaFuncSetAttribute(lse_mma_k, cudaFuncAttributeMaxDynamicSharedMemorySize, SMEM_BYTES);

    init_detect_k<<<1, 256>>>(lw);
    cvt_k<<<N_TOT / 16, 256>>>(f, lw);
    lse_mma_k<<<NCTA, 128, SMEM_BYTES>>>();
    fin_k<<<FIN_BLOCKS, 256>>>(f);
    fin2_k<<<1, 128>>>(out);
}

// round 13
// speedup vs baseline: 5.9297x; 1.0159x over previous
#include <cuda_runtime.h>
#include <cuda_bf16.h>
#include <math.h>
#include <stdint.h>

// ---------------------------------------------------------------------------
// Problem constants
// ---------------------------------------------------------------------------
#define N_TOT 8192
#define D 128
#define TEMP_INV (1.0f/0.07f)
#define SCALE_LOG2 (1.44269504088896340736f/0.07f)   /* log2(e)/T */
#define LN2F 0.6931471805599453f
#define NCTA 608            /* 4 CTAs per SM x 152 SMs */
#define NUNITS 2048         /* 64 I-blocks x 32 units (unit = 256 J cols) */
#define NSLOT 16            /* slot = cta & 15; span per I-block <= 12 */
#define FIN_BLOCKS 256

// SMEM: A = 128 rows x 128 bf16 (resident), B = 32-row subtiles, dbl-buffered.
#define PKB 272
#define A_TB (128 * PKB)        /* 34816 */
#define B_TB (32 * PKB)         /* 8704  */
#define OFF_A 0
#define OFF_B(b) (A_TB + (b)*B_TB)
#define SMEM_BYTES (A_TB + 2*B_TB)   /* 52224 -> 4 CTAs/SM */

// ---------------------------------------------------------------------------
// Device scratch
// ---------------------------------------------------------------------------
__device__ __nv_bfloat16 g_hi[N_TOT * D];
__device__ float    g_norm[N_TOT];      /* |f_i|^2, fp32 exact */
__device__ float    g_G[2][D];
__device__ int      g_C[2];
__device__ int      g_cls[N_TOT];       /* 0 invalid, 1 class0, 2 class1 */
__device__ float    g_pm[NSLOT][N_TOT]; /* log2-domain partial max */
__device__ float    g_ps[NSLOT][N_TOT];
__device__ float    g_bsum[FIN_BLOCKS];
__device__ int      g_fin_count;
__device__ int      g_is64;

// ---------------------------------------------------------------------------
// Family-safe PTX helpers
// ---------------------------------------------------------------------------
__device__ __forceinline__ uint32_t smem_u32(const void* p) {
    uint32_t a;
    asm("{ .reg .u64 t; cvta.to.shared.u64 t, %1; cvt.u32.u64 %0, t; }" : "=r"(a) : "l"(p));
    return a;
}
__device__ __forceinline__ void ldsm4(uint32_t* r, uint32_t addr) {
    asm volatile("ldmatrix.sync.aligned.m8n8.x4.shared.b16 {%0,%1,%2,%3}, [%4];"
                 : "=r"(r[0]), "=r"(r[1]), "=r"(r[2]), "=r"(r[3]) : "r"(addr));
}
__device__ __forceinline__ void mma16816(float* c, const uint32_t* a, uint32_t b0, uint32_t b1) {
    asm volatile("mma.sync.aligned.m16n8k16.row.col.f32.bf16.bf16.f32 "
                 "{%0,%1,%2,%3}, {%4,%5,%6,%7}, {%8,%9}, {%0,%1,%2,%3};"
                 : "+f"(c[0]), "+f"(c[1]), "+f"(c[2]), "+f"(c[3])
                 : "r"(a[0]), "r"(a[1]), "r"(a[2]), "r"(a[3]), "r"(b0), "r"(b1));
}
__device__ __forceinline__ void cp16(uint32_t dst, const void* src) {
    asm volatile("cp.async.cg.shared.global [%0], [%1], 16;" :: "r"(dst), "l"(src));
}
#define CP_COMMIT() asm volatile("cp.async.commit_group;" ::: "memory")
#define CP_WAIT(n)  asm volatile("cp.async.wait_group %0;" :: "n"(n) : "memory")

__device__ __forceinline__ float ex2(float x) {
    float y;
    asm("ex2.approx.ftz.f32 %0, %1;" : "=f"(y) : "f"(x));
    return y;
}

// online-softmax merge, log2 domain
__device__ __forceinline__ void comb2(float& m, float& s, float m2, float s2) {
    float M = fmaxf(m, m2);
    float S;
    if (M == -INFINITY) S = 0.f;
    else S = ((m  == -INFINITY) ? 0.f : s  * ex2(m  - M))
           + ((m2 == -INFINITY) ? 0.f : s2 * ex2(m2 - M));
    m = M; s = S;
}

// cp.async nrows x 128 bf16 rows into padded smem (16B chunks, 16 per row)
__device__ __forceinline__ void cp_rows(const __nv_bfloat16* __restrict__ src, int rowBase,
                                        uint32_t dstBase, int tid, int nthr, int nrows) {
    for (int i = tid; i < nrows * 16; i += nthr) {
        int row = i >> 4, c = i & 15;
        cp16(dstBase + row * PKB + c * 16, src + (size_t)(rowBase + row) * D + c * 8);
    }
}

// ---------------------------------------------------------------------------
// Kernel 0: zero class sums/counts + fin counter + detect label word width.
// ---------------------------------------------------------------------------
__global__ void init_detect_k(const int* __restrict__ lw) {
    int t = threadIdx.x;
    if (t < 2 * D) ((float*)g_G)[t] = 0.0f;
    if (t < 2)     g_C[t] = 0;
    if (t == 2)    g_fin_count = 0;
    int local = 0;
    for (int i = 1 + 2 * t; i < N_TOT; i += 2 * 256) local |= lw[i];
    __shared__ int anynz;
    if (t == 0) anynz = 0;
    __syncthreads();
    if (local) atomicOr(&anynz, 1);
    __syncthreads();
    if (t == 0) g_is64 = anynz ? 0 : 1;
}

// ---------------------------------------------------------------------------
// Kernel 1 (fused): bf16 split + exact fp32 norms + class code +
// per-class sums/counts (shared staging) + partial-slot init.
// ---------------------------------------------------------------------------
__global__ void cvt_k(const float* __restrict__ f, const int* __restrict__ lw) {
    __shared__ float sG[2 * D];
    __shared__ int   sC[2];
    const int tid = threadIdx.x, w = tid >> 5, lane = tid & 31;
    const int row0 = blockIdx.x * 16 + w * 2;
    const int is64 = g_is64;

    sG[tid] = 0.f;
    if (tid < 2) sC[tid] = 0;
    __syncthreads();

    #pragma unroll
    for (int rr = 0; rr < 2; rr++) {
        int r = row0 + rr;
        float4 v = ((const float4*)(f + (size_t)r * D))[lane];
        __nv_bfloat16 hx = __float2bfloat16(v.x);
        __nv_bfloat16 hy = __float2bfloat16(v.y);
        __nv_bfloat16 hz = __float2bfloat16(v.z);
        __nv_bfloat16 hw = __float2bfloat16(v.w);
        __nv_bfloat162 hp0 = __halves2bfloat162(hx, hy);
        __nv_bfloat162 hp1 = __halves2bfloat162(hz, hw);
        uint2 H;
        H.x = *reinterpret_cast<uint32_t*>(&hp0);
        H.y = *reinterpret_cast<uint32_t*>(&hp1);
        *(uint2*)(g_hi + (size_t)r * D + lane * 4) = H;

        float sq = v.x * v.x + v.y * v.y + v.z * v.z + v.w * v.w;
        #pragma unroll
        for (int off = 16; off > 0; off >>= 1)
            sq += __shfl_xor_sync(0xffffffffu, sq, off);

        uint32_t bal = __ballot_sync(0xffffffffu,
            (v.x != 0.f) || (v.y != 0.f) || (v.z != 0.f) || (v.w != 0.f));
        int lab = is64 ? lw[2 * r] : lw[r];
        int cls = bal ? (lab + 1) : 0;
        if (lane == 0) {
            g_cls[r]  = cls;
            g_norm[r] = sq;
        }
        if (cls) {
            float* dst = sG + (cls - 1) * D + lane * 4;
            atomicAdd(dst + 0, v.x);
            atomicAdd(dst + 1, v.y);
            atomicAdd(dst + 2, v.z);
            atomicAdd(dst + 3, v.w);
            if (lane == 0) atomicAdd(&sC[cls - 1], 1);
        }
    }
    __syncthreads();
    atomicAdd(&((float*)g_G)[tid], sG[tid]);
    if (tid < 2) atomicAdd(&g_C[tid], sC[tid]);

    // init partial slots: NSLOT*N_TOT = 131072 = grid size exactly
    int gt = blockIdx.x * 256 + tid;
    ((float*)g_pm)[gt] = -INFINITY;
    ((float*)g_ps)[gt] = 0.f;
}

// ---------------------------------------------------------------------------
// Kernel 2: pure-bf16 GEMM (HMMA) + fused online logsumexp (log2 domain).
// 608 CTAs x 128 threads (4/SM). Diagonal excluded (merged exactly in fin).
// (unchanged from R12 — protected win)
// ---------------------------------------------------------------------------
__global__ void __launch_bounds__(128, 4) lse_mma_k() {
    extern __shared__ char smc[];
    const uint32_t base = smem_u32(smc);

    const int tid  = threadIdx.x;
    const int wid  = tid >> 5;
    const int lane = tid & 31;
    const int wrow = wid * 32;
    const int lrow = (lane & 7) + ((lane >> 3) & 1) * 8;
    const int lkof = (lane >> 4) * 16;

    const int c  = blockIdx.x;
    const int u0 = (c * NUNITS) / NCTA;
    const int u1 = ((c + 1) * NUNITS) / NCTA;

    int nseg, sI[2], sA[2], sB[2];
    {
        int I0 = u0 >> 5, bnd = (I0 + 1) << 5;
        int e1 = (u1 < bnd) ? u1 : bnd;
        sI[0] = I0;
        sA[0] = (u0 & 31) * 8;
        sB[0] = sA[0] + (e1 - u0) * 8;
        if (u1 > bnd) { sI[1] = I0 + 1; sA[1] = 0; sB[1] = (u1 - bnd) * 8; nseg = 2; }
        else nseg = 1;
    }
    const int slot = c & (NSLOT - 1);

    const uint32_t aB = base + OFF_A + (wrow + lrow) * PKB + lkof;

    for (int g = 0; g < nseg; g++) {
        const int rowI = sI[g] * 128;
        const int jA = sA[g], jB = sB[g];

        cp_rows(g_hi, rowI, base + OFF_A, tid, 128, 128);
        cp_rows(g_hi, jA * 32, base + OFF_B(0), tid, 128, 32);
        CP_COMMIT();

        float mrun[4], srun[4];
        #pragma unroll
        for (int i = 0; i < 4; i++) { mrun[i] = 0.f; srun[i] = 0.f; }

        for (int s = jA; s < jB; s++) {
            const int p = (s - jA) & 1, q = p ^ 1;

            CP_WAIT(0);
            __syncthreads();

            if (s + 1 < jB) {
                cp_rows(g_hi, (s + 1) * 32, base + OFF_B(q), tid, 128, 32);
                CP_COMMIT();
            }

            float acc[2][4][4];
            #pragma unroll
            for (int mb = 0; mb < 2; mb++)
                #pragma unroll
                for (int nt = 0; nt < 4; nt++)
                    #pragma unroll
                    for (int cc = 0; cc < 4; cc++) acc[mb][nt][cc] = 0.f;

            const uint32_t bB = base + OFF_B(p) + lrow * PKB + lkof;

            #pragma unroll
            for (int ks = 0; ks < 8; ks++) {
                uint32_t aH[2][4];
                ldsm4(aH[0], aB + ks * 32);
                ldsm4(aH[1], aB + 16 * PKB + ks * 32);
                #pragma unroll
                for (int np = 0; np < 2; np++) {
                    uint32_t bH[4];
                    ldsm4(bH, bB + np * (16 * PKB) + ks * 32);
                    #pragma unroll
                    for (int mb = 0; mb < 2; mb++) {
                        mma16816(acc[mb][np * 2 + 0], aH[mb], bH[0], bH[2]);
                        mma16816(acc[mb][np * 2 + 1], aH[mb], bH[1], bH[3]);
                    }
                }
            }

            if (s * 32 == rowI + wrow) {
                #pragma unroll
                for (int mb = 0; mb < 2; mb++)
                    #pragma unroll
                    for (int nt = 0; nt < 4; nt++)
                        #pragma unroll
                        for (int cc = 0; cc < 4; cc++) {
                            int rl = mb * 16 + ((cc >> 1) << 3) + (lane >> 2);
                            int cl = nt * 8 + ((lane & 3) << 1) + (cc & 1);
                            if (rl == cl) acc[mb][nt][cc] = -INFINITY;
                        }
            }

            #pragma unroll
            for (int mb = 0; mb < 2; mb++) {
                float tm0 = -INFINITY, tm1 = -INFINITY;
                #pragma unroll
                for (int nt = 0; nt < 4; nt++) {
                    tm0 = fmaxf(tm0, fmaxf(acc[mb][nt][0], acc[mb][nt][1]));
                    tm1 = fmaxf(tm1, fmaxf(acc[mb][nt][2], acc[mb][nt][3]));
                }
                float ts0 = tm0 * SCALE_LOG2, ts1 = tm1 * SCALE_LOG2;
                int i0 = mb * 2, i1 = i0 + 1;
                if (ts0 > mrun[i0]) { srun[i0] *= ex2(mrun[i0] - ts0); mrun[i0] = ts0; }
                if (ts0 >= mrun[i0] - 64.0f) {
                    float a0 = 0.f, a1 = 0.f;
                    #pragma unroll
                    for (int nt = 0; nt < 4; nt++) {
                        a0 += ex2(fmaf(acc[mb][nt][0], SCALE_LOG2, -mrun[i0]));
                        a1 += ex2(fmaf(acc[mb][nt][1], SCALE_LOG2, -mrun[i0]));
                    }
                    srun[i0] += a0 + a1;
                }
                if (ts1 > mrun[i1]) { srun[i1] *= ex2(mrun[i1] - ts1); mrun[i1] = ts1; }
                if (ts1 >= mrun[i1] - 64.0f) {
                    float b0 = 0.f, b1 = 0.f;
                    #pragma unroll
                    for (int nt = 0; nt < 4; nt++) {
                        b0 += ex2(fmaf(acc[mb][nt][2], SCALE_LOG2, -mrun[i1]));
                        b1 += ex2(fmaf(acc[mb][nt][3], SCALE_LOG2, -mrun[i1]));
                    }
                    srun[i1] += b0 + b1;
                }
            }
        }

        #pragma unroll
        for (int i = 0; i < 4; i++) {
            #pragma unroll
            for (int off = 1; off <= 2; off <<= 1) {
                float mm = __shfl_xor_sync(0xffffffffu, mrun[i], off);
                float ss = __shfl_xor_sync(0xffffffffu, srun[i], off);
                comb2(mrun[i], srun[i], mm, ss);
            }
        }
        if ((lane & 3) == 0) {
            int r0 = rowI + wrow + (lane >> 2);
            g_pm[slot][r0]      = mrun[0];
            g_ps[slot][r0]      = srun[0];
            g_pm[slot][r0 + 8]  = mrun[1];
            g_ps[slot][r0 + 8]  = srun[1];
            g_pm[slot][r0 + 16] = mrun[2];
            g_ps[slot][r0 + 16] = srun[2];
            g_pm[slot][r0 + 24] = mrun[3];
            g_ps[slot][r0 + 24] = srun[3];
        }
        __syncthreads();
    }
}

// ---------------------------------------------------------------------------
// Kernel 3: per-anchor finalize + fused final reduction (last block).
// 256 blocks x 256 threads; 8 threads/anchor: each combines 2 slots and a
// 16-element dot slice, octet-butterfly merge, exact diagonal from fp32 norm.
// Last block (device counter) does the deterministic 256-way final sum.
// ---------------------------------------------------------------------------
__global__ void fin_k(const float* __restrict__ f, float* __restrict__ out) {
    __shared__ float Gs[2 * D];
    __shared__ float red[32];
    __shared__ int   lastFlag;
    const int t = threadIdx.x;
    Gs[t] = ((const float*)g_G)[t];
    __syncthreads();

    const int aIdx = t >> 3;                 // 32 anchors per block
    const int ot   = t & 7;                  // octet thread
    const int i    = blockIdx.x * 32 + aIdx;

    int cls = g_cls[i];

    // combine 2 slots per thread
    float M = g_pm[ot][i], S = g_ps[ot][i];
    comb2(M, S, g_pm[ot + 8][i], g_ps[ot + 8][i]);

    // 16-element dot slice
    float dot = 0.f;
    {
        int lab = (cls == 2) ? 1 : 0;
        const float4* fr = (const float4*)(f + (size_t)i * D) + ot * 4;
        const float4* gr = (const float4*)(Gs + lab * D) + ot * 4;
        #pragma unroll
        for (int k = 0; k < 4; k++) {
            float4 a = fr[k]; float4 g = gr[k];
            dot = fmaf(a.x, g.x, dot); dot = fmaf(a.y, g.y, dot);
            dot = fmaf(a.z, g.z, dot); dot = fmaf(a.w, g.w, dot);
        }
    }

    // octet butterfly
    #pragma unroll
    for (int off = 1; off <= 4; off <<= 1) {
        float mm = __shfl_xor_sync(0xffffffffu, M, off);
        float ss = __shfl_xor_sync(0xffffffffu, S, off);
        comb2(M, S, mm, ss);
        dot += __shfl_xor_sync(0xffffffffu, dot, off);
    }

    float term = 0.f;
    if (ot == 0 && cls != 0) {
        comb2(M, S, g_norm[i] * SCALE_LOG2, 1.0f);   // exact diagonal
        float lse = (M + log2f(S)) * LN2F;
        float cnt = (float)g_C[(cls == 2) ? 1 : 0];
        term = (cnt * lse - dot * TEMP_INV) * (1.0f / 128.0f);
    }

    // block reduce 32 anchor terms (lane ot==0 of each octet holds term)
    if (ot == 0) red[aIdx] = term;
    __syncthreads();
    if (t < 32) {
        float v = red[t];
        #pragma unroll
        for (int off = 16; off > 0; off >>= 1)
            v += __shfl_xor_sync(0xffffffffu, v, off);
        if (t == 0) {
            g_bsum[blockIdx.x] = v;
            __threadfence();
            int old = atomicAdd(&g_fin_count, 1);
            lastFlag = (old == FIN_BLOCKS - 1);
        }
    }
    __syncthreads();

    // last block: deterministic final sum over the 256 block results
    if (lastFlag && t < 32) {
        float v = 0.f;
        #pragma unroll
        for (int k = 0; k < FIN_BLOCKS / 32; k++)
            v += g_bsum[t + k * 32];
        #pragma unroll
        for (int off = 16; off > 0; off >>= 1)
            v += __shfl_xor_sync(0xffffffffu, v, off);
        if (t == 0) out[0] = v * (1.0f / 256.0f);
    }
}

// ---------------------------------------------------------------------------
extern "C" void kernel_launch(void* const* d_in, const int* in_sizes, int n_in,
                              void* d_out, int out_size) {
    const float* f  = (const float*)d_in[0];
    const int*   lw = (const int*)d_in[1];
    float* out = (float*)d_out;

    cudaFuncSetAttribute(lse_mma_k, cudaFuncAttributeMaxDynamicSharedMemorySize, SMEM_BYTES);

    init_detect_k<<<1, 256>>>(lw);
    cvt_k<<<N_TOT / 16, 256>>>(f, lw);
    lse_mma_k<<<NCTA, 128, SMEM_BYTES>>>();
    fin_k<<<FIN_BLOCKS, 256>>>(f, out);
}